// round 1
// baseline (speedup 1.0000x reference)
#include <cuda_runtime.h>
#include <math.h>
#include <float.h>

#define NB 148
#define NT 256
#define WPB (NT/32)
#define NWARPS (NB*WPB)
#define HD 1024

// ---- output layout (tuple flattened in order) ----
#define OFF_PA 0        // pred_actions [2,2513]
#define OFF_PV 5026     // pred_verbs   [2,125]
#define OFF_PN 5276     // pred_nouns   [2,352]
#define OFF_PF 5980     // pfeat        [2,1024]
#define OFF_PG 8028     // pgoal        [2,1024]
#define OFF_F2 10076    // f2in         [1,1024]
#define OFF_CA 11100    // cur_action   [1,2513]

// ---- scratch (device globals; no allocation allowed) ----
__device__ __align__(16) float s_maxpart[NB][HD];
__device__ __align__(16) float s_maxv[HD];
__device__ __align__(16) float s_fs[HD];
__device__ __align__(16) float s_gh[5][HD];        // goal layer outputs; s_gh[4] = goal
__device__ __align__(16) float s_rb[4*HD];
__device__ __align__(16) float s_xpart[2][4*HD];
__device__ __align__(16) float s_base[2][HD];
__device__ __align__(16) float s_c[HD];
__device__ __align__(16) float s_a[2][10][HD];
__device__ __align__(16) float s_f[2][10][HD];
__device__ __align__(16) float s_diff2[2][10][HD];
__device__ float s_d[2][10];
__device__ float s_bd0;
__device__ __align__(16) float s_pa[2][HD];
__device__ unsigned s_barGen = 0;
__device__ unsigned s_barCnt = 0;

__device__ __forceinline__ void gridbar() {
    __syncthreads();
    if (threadIdx.x == 0) {
        __threadfence();
        unsigned gen = *((volatile unsigned*)&s_barGen);
        __threadfence();
        unsigned a = atomicAdd(&s_barCnt, 1u);
        if (a == NB - 1) {
            s_barCnt = 0;
            __threadfence();
            atomicAdd(&s_barGen, 1u);
        } else {
            while (*((volatile unsigned*)&s_barGen) == gen) { __nanosleep(32); }
        }
        __threadfence();
    }
    __syncthreads();
}

__device__ __forceinline__ float sigf(float x) { return 1.0f / (1.0f + expf(-x)); }

// warp-collective dot of a 1024-float row with a 1024-float vector; result in all lanes
__device__ __forceinline__ float dot1024(const float* __restrict__ w,
                                         const float* __restrict__ x, int lane) {
    const float4* w4 = (const float4*)w;
    const float4* x4 = (const float4*)x;
    float acc = 0.0f;
#pragma unroll
    for (int i = 0; i < 8; ++i) {
        float4 a = w4[lane + (i << 5)];
        float4 b = x4[lane + (i << 5)];
        acc = fmaf(a.x, b.x, acc);
        acc = fmaf(a.y, b.y, acc);
        acc = fmaf(a.z, b.z, acc);
        acc = fmaf(a.w, b.w, acc);
    }
#pragma unroll
    for (int o = 16; o; o >>= 1) acc += __shfl_xor_sync(0xffffffffu, acc, o);
    return acc;
}

// per-warp deterministic sum of a 1024-float buffer (result in all lanes)
__device__ __forceinline__ float warp_sum1024(const float* __restrict__ v, int lane) {
    float acc = 0.0f;
#pragma unroll
    for (int i = 0; i < 32; ++i) acc += v[lane + (i << 5)];
#pragma unroll
    for (int o = 16; o; o >>= 1) acc += __shfl_xor_sync(0xffffffffu, acc, o);
    return acc;
}

// expansion-1 scan: i_star = argmin(s1), bd1 = running min of d. d1_9 computed from diff2.
__device__ __forceinline__ int scan_e1(int lane, float* d9_out, float* bd1_out) {
    float d9 = warp_sum1024(s_diff2[0][9], lane) * (1.0f / 1024.0f);
    float bd = s_bd0;
    float best = FLT_MAX; int istar = 0;
#pragma unroll
    for (int jj = 0; jj < 10; ++jj) {
        float dj = (jj == 9) ? d9 : s_d[0][jj];
        float s = bd - dj;
        if (s < best) { best = s; istar = jj; }
        if (dj < bd) bd = dj;
    }
    *d9_out = d9; *bd1_out = bd;
    return istar;
}

// one step-phase of an expansion: computes h_j (j<10) and nf_{j-1} (j>=1); d_{j-2} (j>=2)
__device__ void expand_phase(int e, int j,
                             const float* __restrict__ rW_hh,
                             const float* __restrict__ Wp,
                             const float* __restrict__ goal,
                             int gwid, int lane) {
    for (int u = gwid; u < 2049; u += NWARPS) {
        if (u < 1024) {
            if (j < 10) {
                float di = 0.f, dfg = 0.f, dg = 0.f, dog = 0.f;
                if (j > 0) {
                    const float* hp = s_a[e][j - 1];
                    di  = dot1024(rW_hh + (size_t)u * HD, hp, lane);
                    dfg = dot1024(rW_hh + (size_t)(u + 1024) * HD, hp, lane);
                    dg  = dot1024(rW_hh + (size_t)(u + 2048) * HD, hp, lane);
                    dog = dot1024(rW_hh + (size_t)(u + 3072) * HD, hp, lane);
                }
                if (lane == 0) {
                    float gi = di  + s_xpart[e][u];
                    float gf = dfg + s_xpart[e][u + 1024];
                    float gg = dg  + s_xpart[e][u + 2048];
                    float go = dog + s_xpart[e][u + 3072];
                    float cn = sigf(gi) * tanhf(gg);
                    if (j > 0) cn += sigf(gf) * s_c[u];
                    s_c[u] = cn;
                    s_a[e][j][u] = sigf(go) * tanhf(cn);
                }
            }
        } else if (u < 2048) {
            if (j >= 1) {
                int r = u - 1024;
                float v = dot1024(Wp + (size_t)r * 3072 + 1024, s_a[e][j - 1], lane);
                if (lane == 0) {
                    v = fmaxf(v + s_base[e][r], 0.0f);
                    s_f[e][j - 1][r] = v;
                    float df = v - goal[r];
                    s_diff2[e][j - 1][r] = df * df;
                }
            }
        } else { // u == 2048 : reduce d_{j-2}
            if (j >= 2) {
                int k = j - 2;
                float acc = warp_sum1024(s_diff2[e][k], lane);
                if (lane == 0) s_d[e][k] = acc * (1.0f / 1024.0f);
            }
        }
    }
    gridbar();
}

__global__ void __launch_bounds__(NT)
va_kernel(const float* __restrict__ tsn,
          const float* __restrict__ W_fe,  const float* __restrict__ b_fe,
          const float* __restrict__ gW_ih0,const float* __restrict__ gW_ihR,
          const float* __restrict__ gb_ih, const float* __restrict__ gb_hh,
          const float* __restrict__ rW_ih, const float* __restrict__ rW_hh,
          const float* __restrict__ rb_ih, const float* __restrict__ rb_hh,
          const float* __restrict__ Wp,    const float* __restrict__ bp,
          const float* __restrict__ We2a,  const float* __restrict__ be2a,
          const float* __restrict__ We2v,  const float* __restrict__ be2v,
          const float* __restrict__ We2n,  const float* __restrict__ be2n,
          float* __restrict__ out) {
    const int tid  = threadIdx.x;
    const int lane = tid & 31;
    const int gwid = blockIdx.x * WPB + (tid >> 5);
    const int gtid = blockIdx.x * NT + tid;

    // ---------- P0: max-pool partials (rows split across blocks) + rb ----------
    {
        const int r0 = blockIdx.x * 28;
        const int r1 = min(4096, r0 + 28);
        float4 m = make_float4(-FLT_MAX, -FLT_MAX, -FLT_MAX, -FLT_MAX);
        const float4* t4 = (const float4*)tsn;
        for (int r = r0; r < r1; ++r) {
            float4 v = t4[r * 256 + tid];
            m.x = fmaxf(m.x, v.x); m.y = fmaxf(m.y, v.y);
            m.z = fmaxf(m.z, v.z); m.w = fmaxf(m.w, v.w);
        }
        ((float4*)s_maxpart[blockIdx.x])[tid] = m;
        for (int i = gtid; i < 4096; i += NB * NT) s_rb[i] = rb_ih[i] + rb_hh[i];
    }
    gridbar();

    // ---------- P1: finish max ----------
    for (int c = gtid; c < HD; c += NB * NT) {
        float m = -FLT_MAX;
        for (int b = 0; b < NB; ++b) m = fmaxf(m, s_maxpart[b][c]);
        s_maxv[c] = m;
    }
    gridbar();

    // ---------- P2: fs = W_fe @ maxv + b_fe ----------
    for (int u = gwid; u < HD; u += NWARPS) {
        float v = dot1024(W_fe + (size_t)u * HD, s_maxv, lane);
        if (lane == 0) s_fs[u] = v + b_fe[u];
    }
    gridbar();

    // ---------- P3: goal LSTM layer 0 (c=0 -> skip f-gate) + cur_action ----------
    for (int u = gwid; u < 1024 + 2513; u += NWARPS) {
        if (u < 1024) {
            float di = dot1024(gW_ih0 + (size_t)u * 2048, s_fs, lane);
            float dg = dot1024(gW_ih0 + (size_t)(u + 2048) * 2048, s_fs, lane);
            float dog= dot1024(gW_ih0 + (size_t)(u + 3072) * 2048, s_fs, lane);
            if (lane == 0) {
                float gi = di  + gb_ih[u] + gb_hh[u];
                float gg = dg  + gb_ih[u + 2048] + gb_hh[u + 2048];
                float go = dog + gb_ih[u + 3072] + gb_hh[u + 3072];
                float cn = sigf(gi) * tanhf(gg);
                s_gh[0][u] = sigf(go) * tanhf(cn);
            }
        } else {
            int r = u - 1024;
            float v = dot1024(We2a + (size_t)r * HD, s_fs, lane);
            if (lane == 0) out[OFF_CA + r] = v + be2a[r];
        }
    }
    gridbar();

    // ---------- P4..P7: goal LSTM layers 1..4 ----------
    for (int l = 1; l <= 4; ++l) {
        const float* Wl = gW_ihR + (size_t)(l - 1) * 4096 * 1024;
        const float* xin = s_gh[l - 1];
        const float* bi = gb_ih + (size_t)l * 4096;
        const float* bh = gb_hh + (size_t)l * 4096;
        for (int u = gwid; u < 1024; u += NWARPS) {
            float di = dot1024(Wl + (size_t)u * HD, xin, lane);
            float dg = dot1024(Wl + (size_t)(u + 2048) * HD, xin, lane);
            float dog= dot1024(Wl + (size_t)(u + 3072) * HD, xin, lane);
            if (lane == 0) {
                float gi = di  + bi[u] + bh[u];
                float gg = dg  + bi[u + 2048] + bh[u + 2048];
                float go = dog + bi[u + 3072] + bh[u + 3072];
                float cn = sigf(gi) * tanhf(gg);
                s_gh[l][u] = sigf(go) * tanhf(cn);
            }
        }
        gridbar();
    }
    const float* goal = s_gh[4];

    // ---------- P8: expansion-1 pre (a_in = 0) ----------
    for (int u = gwid; u < 4096 + 1024 + 1; u += NWARPS) {
        if (u < 4096) {
            float v = dot1024(rW_ih + (size_t)u * 2048 + 1024, s_fs, lane);
            if (lane == 0) s_xpart[0][u] = v + s_rb[u];
        } else if (u < 5120) {
            int r = u - 4096;
            float v = dot1024(Wp + (size_t)r * 3072, s_fs, lane)
                    + dot1024(Wp + (size_t)r * 3072 + 2048, goal, lane);
            if (lane == 0) s_base[0][r] = v + bp[r];
        } else { // bd0
            float acc = 0.0f;
#pragma unroll
            for (int i = lane; i < HD; i += 32) {
                float df = s_fs[i] - goal[i];
                acc = fmaf(df, df, acc);
            }
#pragma unroll
            for (int o = 16; o; o >>= 1) acc += __shfl_xor_sync(0xffffffffu, acc, o);
            if (lane == 0) s_bd0 = acc * (1.0f / 1024.0f);
        }
    }
    gridbar();

    // ---------- Expansion 1 (11 phases) ----------
    for (int j = 0; j <= 10; ++j) expand_phase(0, j, rW_hh, Wp, goal, gwid, lane);

    // ---------- E2_pre: pick i_star, build xpart2/base2, emit f2in ----------
    {
        float d9, bd1;
        int istar = scan_e1(lane, &d9, &bd1);
        if (gwid == 0 && lane == 0) s_d[0][9] = d9;
        const float* a2in = s_a[0][istar];
        const float* f2in = s_f[0][istar];
        for (int u = gwid; u < 4096 + 1024 + 1; u += NWARPS) {
            if (u < 4096) {
                float v = dot1024(rW_ih + (size_t)u * 2048, a2in, lane)
                        + dot1024(rW_ih + (size_t)u * 2048 + 1024, f2in, lane);
                if (lane == 0) s_xpart[1][u] = v + s_rb[u];
            } else if (u < 5120) {
                int r = u - 4096;
                float v = dot1024(Wp + (size_t)r * 3072, f2in, lane)
                        + dot1024(Wp + (size_t)r * 3072 + 2048, goal, lane);
                if (lane == 0) s_base[1][r] = v + bp[r];
            } else {
                for (int i = lane; i < HD; i += 32) out[OFF_F2 + i] = f2in[i];
            }
        }
    }
    gridbar();

    // ---------- Expansion 2 (11 phases) ----------
    for (int j = 0; j <= 10; ++j) expand_phase(1, j, rW_hh, Wp, goal, gwid, lane);

    // ---------- P_pa: full score scan + top-2, build pa/pfeat/pgoal ----------
    if (gwid < 3) {
        // expansion-1 scan (s_d[0][9] stored)
        float bd = s_bd0, best = FLT_MAX; int istar = 0;
        float s1[10];
#pragma unroll
        for (int jj = 0; jj < 10; ++jj) {
            float dj = s_d[0][jj];
            s1[jj] = bd - dj;
            if (s1[jj] < best) { best = s1[jj]; istar = jj; }
            if (dj < bd) bd = dj;
        }
        float d2_9 = warp_sum1024(s_diff2[1][9], lane) * (1.0f / 1024.0f);
        float s2[10];
#pragma unroll
        for (int jj = 0; jj < 10; ++jj) {
            float dj = (jj == 9) ? d2_9 : s_d[1][jj];
            s2[jj] = bd - dj;
            if (dj < bd) bd = dj;
        }
        float b0 = FLT_MAX, b1 = FLT_MAX; int i0 = 0, i1 = 0;
#pragma unroll
        for (int k = 0; k < 20; ++k) {
            float v = (k < 10) ? ((k == istar) ? FLT_MAX : s1[k]) : s2[k - 10];
            if (v < b0) { b1 = b0; i1 = i0; b0 = v; i0 = k; }
            else if (v < b1) { b1 = v; i1 = k; }
        }
        if (gwid < 2) {
            int idx = (gwid == 0) ? i0 : i1;
            const float* a2in = s_a[0][istar];
            const float* f2in = s_f[0][istar];
            for (int i = lane; i < HD; i += 32) {
                float pa, pf;
                if (idx < 10) {
                    pa = s_a[0][idx][i] / 2.0f;
                    pf = (s_fs[i] + s_f[0][idx][i]) / 2.0f;
                } else {
                    int jd = idx - 10;
                    pa = (a2in[i] + s_a[1][jd][i]) / 3.0f;
                    pf = (s_fs[i] + f2in[i] + s_f[1][jd][i]) / 3.0f;
                }
                s_pa[gwid][i] = pa;
                out[OFF_PF + gwid * HD + i] = pf;
            }
        } else { // gwid == 2: pgoal
            for (int i = lane; i < HD; i += 32) {
                out[OFF_PG + i] = goal[i];
                out[OFF_PG + HD + i] = goal[i];
            }
        }
    }
    gridbar();

    // ---------- P_pred: final prediction matvecs ----------
    for (int u = gwid; u < 5980; u += NWARPS) {
        const float* W; const float* bias; int i, r, off, rows;
        if (u < 5026)      { i = u / 2513;            r = u % 2513;            W = We2a; bias = be2a; off = OFF_PA; rows = 2513; }
        else if (u < 5276) { int lu = u - 5026; i = lu / 125; r = lu % 125;    W = We2v; bias = be2v; off = OFF_PV; rows = 125; }
        else               { int lu = u - 5276; i = lu / 352; r = lu % 352;    W = We2n; bias = be2n; off = OFF_PN; rows = 352; }
        float v = dot1024(W + (size_t)r * HD, s_pa[i], lane);
        if (lane == 0) out[off + i * rows + r] = v + bias[r];
    }
}

extern "C" void kernel_launch(void* const* d_in, const int* in_sizes, int n_in,
                              void* d_out, int out_size) {
    const float* tsn    = (const float*)d_in[0];
    const float* W_fe   = (const float*)d_in[1];
    const float* b_fe   = (const float*)d_in[2];
    const float* gW_ih0 = (const float*)d_in[3];
    const float* gW_ihR = (const float*)d_in[4];
    // d_in[5] = gW_hh : multiplied by zero hidden state everywhere -> unused
    const float* gb_ih  = (const float*)d_in[6];
    const float* gb_hh  = (const float*)d_in[7];
    const float* rW_ih  = (const float*)d_in[8];
    const float* rW_hh  = (const float*)d_in[9];
    const float* rb_ih  = (const float*)d_in[10];
    const float* rb_hh  = (const float*)d_in[11];
    const float* Wp     = (const float*)d_in[12];
    const float* bp     = (const float*)d_in[13];
    const float* We2a   = (const float*)d_in[14];
    const float* be2a   = (const float*)d_in[15];
    const float* We2v   = (const float*)d_in[16];
    const float* be2v   = (const float*)d_in[17];
    const float* We2n   = (const float*)d_in[18];
    const float* be2n   = (const float*)d_in[19];

    va_kernel<<<NB, NT>>>(tsn, W_fe, b_fe, gW_ih0, gW_ihR, gb_ih, gb_hh,
                          rW_ih, rW_hh, rb_ih, rb_hh, Wp, bp,
                          We2a, be2a, We2v, be2v, We2n, be2n,
                          (float*)d_out);
}

// round 2
// speedup vs baseline: 1.0653x; 1.0653x over previous
#include <cuda_runtime.h>
#include <math.h>
#include <float.h>

#define NB 148
#define NT 512
#define WPB (NT/32)
#define NWARPS (NB*WPB)
#define HD 1024

// ---- output layout (tuple flattened in order) ----
#define OFF_PA 0        // pred_actions [2,2513]
#define OFF_PV 5026     // pred_verbs   [2,125]
#define OFF_PN 5276     // pred_nouns   [2,352]
#define OFF_PF 5980     // pfeat        [2,1024]
#define OFF_PG 8028     // pgoal        [2,1024]
#define OFF_F2 10076    // f2in         [1,1024]
#define OFF_CA 11100    // cur_action   [1,2513]

// ---- scratch (device globals; no allocation allowed) ----
__device__ __align__(16) float s_maxpart[NB][HD];
__device__ __align__(16) float s_maxv[HD];
__device__ __align__(16) float s_fs[HD];
__device__ __align__(16) float s_gh[5][HD];        // goal layer outputs; s_gh[4] = goal
__device__ __align__(16) float s_rb[4*HD];
__device__ __align__(16) float s_xpart[2][4*HD];
__device__ __align__(16) float s_base[2][HD];
__device__ __align__(16) float s_c[HD];
__device__ __align__(16) float s_a[2][10][HD];
__device__ __align__(16) float s_f[2][10][HD];
__device__ __align__(16) float s_diff2[2][10][HD];
__device__ float s_d[2][10];
__device__ float s_bd0;
__device__ __align__(16) float s_pa[2][HD];
__device__ unsigned s_barGen = 0;
__device__ unsigned s_barCnt = 0;

__device__ __forceinline__ void gridbar() {
    __syncthreads();
    if (threadIdx.x == 0) {
        __threadfence();
        unsigned gen = *((volatile unsigned*)&s_barGen);
        __threadfence();
        unsigned a = atomicAdd(&s_barCnt, 1u);
        if (a == NB - 1) {
            s_barCnt = 0;
            __threadfence();
            atomicAdd(&s_barGen, 1u);
        } else {
            while (*((volatile unsigned*)&s_barGen) == gen) { __nanosleep(32); }
        }
        __threadfence();
    }
    __syncthreads();
}

__device__ __forceinline__ float sigf(float x) { return 1.0f / (1.0f + expf(-x)); }

__device__ __forceinline__ float warp_red(float a) {
#pragma unroll
    for (int o = 16; o; o >>= 1) a += __shfl_xor_sync(0xffffffffu, a, o);
    return a;
}

// warp-collective dot of a 1024-float row with a 1024-float vector; result in all lanes
__device__ __forceinline__ float dot1024(const float* __restrict__ w,
                                         const float* __restrict__ x, int lane) {
    const float4* w4 = (const float4*)w;
    const float4* x4 = (const float4*)x;
    float acc = 0.0f;
#pragma unroll
    for (int i = 0; i < 8; ++i) {
        float4 a = w4[lane + (i << 5)];
        float4 b = x4[lane + (i << 5)];
        acc = fmaf(a.x, b.x, acc);
        acc = fmaf(a.y, b.y, acc);
        acc = fmaf(a.z, b.z, acc);
        acc = fmaf(a.w, b.w, acc);
    }
    return warp_red(acc);
}

// 4 interleaved 1024-dots: rows w, w+S, w+2S, w+3S against x (shared x loads, high MLP)
__device__ __forceinline__ void dot4_1024(const float* __restrict__ w, size_t S,
                                          const float* __restrict__ x, int lane,
                                          float& r0, float& r1, float& r2, float& r3) {
    const float4* x4 = (const float4*)x;
    float a0 = 0.f, a1 = 0.f, a2 = 0.f, a3 = 0.f;
#pragma unroll
    for (int i = 0; i < 8; ++i) {
        int idx = lane + (i << 5);
        float4 xv = x4[idx];
        float4 w0 = ((const float4*)(w))[idx];
        float4 w1 = ((const float4*)(w + S))[idx];
        float4 w2 = ((const float4*)(w + 2 * S))[idx];
        float4 w3 = ((const float4*)(w + 3 * S))[idx];
        a0 = fmaf(w0.x, xv.x, fmaf(w0.y, xv.y, fmaf(w0.z, xv.z, fmaf(w0.w, xv.w, a0))));
        a1 = fmaf(w1.x, xv.x, fmaf(w1.y, xv.y, fmaf(w1.z, xv.z, fmaf(w1.w, xv.w, a1))));
        a2 = fmaf(w2.x, xv.x, fmaf(w2.y, xv.y, fmaf(w2.z, xv.z, fmaf(w2.w, xv.w, a2))));
        a3 = fmaf(w3.x, xv.x, fmaf(w3.y, xv.y, fmaf(w3.z, xv.z, fmaf(w3.w, xv.w, a3))));
    }
    r0 = warp_red(a0); r1 = warp_red(a1); r2 = warp_red(a2); r3 = warp_red(a3);
}

// 3 interleaved 1024-dots with arbitrary row pointers (goal LSTM: i, g, o gates)
__device__ __forceinline__ void dot3_1024(const float* __restrict__ w0,
                                          const float* __restrict__ w1,
                                          const float* __restrict__ w2,
                                          const float* __restrict__ x, int lane,
                                          float& r0, float& r1, float& r2) {
    const float4* x4 = (const float4*)x;
    float a0 = 0.f, a1 = 0.f, a2 = 0.f;
#pragma unroll
    for (int i = 0; i < 8; ++i) {
        int idx = lane + (i << 5);
        float4 xv = x4[idx];
        float4 v0 = ((const float4*)w0)[idx];
        float4 v1 = ((const float4*)w1)[idx];
        float4 v2 = ((const float4*)w2)[idx];
        a0 = fmaf(v0.x, xv.x, fmaf(v0.y, xv.y, fmaf(v0.z, xv.z, fmaf(v0.w, xv.w, a0))));
        a1 = fmaf(v1.x, xv.x, fmaf(v1.y, xv.y, fmaf(v1.z, xv.z, fmaf(v1.w, xv.w, a1))));
        a2 = fmaf(v2.x, xv.x, fmaf(v2.y, xv.y, fmaf(v2.z, xv.z, fmaf(v2.w, xv.w, a2))));
    }
    r0 = warp_red(a0); r1 = warp_red(a1); r2 = warp_red(a2);
}

// two interleaved 1024-dots with different x vectors, summed (concat dots)
__device__ __forceinline__ float dot2x_1024(const float* __restrict__ wa,
                                            const float* __restrict__ xa,
                                            const float* __restrict__ wb,
                                            const float* __restrict__ xb, int lane) {
    float a0 = 0.f, a1 = 0.f;
#pragma unroll
    for (int i = 0; i < 8; ++i) {
        int idx = lane + (i << 5);
        float4 va = ((const float4*)wa)[idx];
        float4 ua = ((const float4*)xa)[idx];
        float4 vb = ((const float4*)wb)[idx];
        float4 ub = ((const float4*)xb)[idx];
        a0 = fmaf(va.x, ua.x, fmaf(va.y, ua.y, fmaf(va.z, ua.z, fmaf(va.w, ua.w, a0))));
        a1 = fmaf(vb.x, ub.x, fmaf(vb.y, ub.y, fmaf(vb.z, ub.z, fmaf(vb.w, ub.w, a1))));
    }
    return warp_red(a0 + a1);
}

// per-warp deterministic sum of a 1024-float buffer (result in all lanes)
__device__ __forceinline__ float warp_sum1024(const float* __restrict__ v, int lane) {
    float acc = 0.0f;
#pragma unroll
    for (int i = 0; i < 32; ++i) acc += v[lane + (i << 5)];
    return warp_red(acc);
}

__device__ __forceinline__ void l2_prefetch(const void* base, size_t bytes,
                                            int widx, int nworkers) {
    const char* p = (const char*)base;
    for (size_t off = (size_t)widx * 128; off < bytes; off += (size_t)nworkers * 128)
        asm volatile("prefetch.global.L2 [%0];" :: "l"(p + off));
}

// expansion-1 scan: i_star = argmin(s1). d1_9 computed from diff2.
__device__ __forceinline__ int scan_e1(int lane, float* d9_out) {
    float d9 = warp_sum1024(s_diff2[0][9], lane) * (1.0f / 1024.0f);
    float bd = s_bd0;
    float best = FLT_MAX; int istar = 0;
#pragma unroll
    for (int jj = 0; jj < 10; ++jj) {
        float dj = (jj == 9) ? d9 : s_d[0][jj];
        float s = bd - dj;
        if (s < best) { best = s; istar = jj; }
        if (dj < bd) bd = dj;
    }
    *d9_out = d9;
    return istar;
}

// one step-phase of an expansion: computes h_j (j<10) and nf_{j-1} (j>=1); d_{j-2} (j>=2)
__device__ void expand_phase(int e, int j,
                             const float* __restrict__ rW_hh,
                             const float* __restrict__ Wp,
                             const float* __restrict__ rW_ih,
                             const float* __restrict__ goal,
                             int gwid, int lane) {
    for (int u = gwid; u < 2049; u += NWARPS) {
        if (u < 1024) {
            if (j < 10) {
                float di = 0.f, dfg = 0.f, dg = 0.f, dog = 0.f;
                if (j > 0)
                    dot4_1024(rW_hh + (size_t)u * HD, (size_t)1024 * 1024,
                              s_a[e][j - 1], lane, di, dfg, dg, dog);
                if (lane == 0) {
                    float gi = di  + s_xpart[e][u];
                    float gf = dfg + s_xpart[e][u + 1024];
                    float gg = dg  + s_xpart[e][u + 2048];
                    float go = dog + s_xpart[e][u + 3072];
                    float cn = sigf(gi) * tanhf(gg);
                    if (j > 0) cn += sigf(gf) * s_c[u];
                    s_c[u] = cn;
                    s_a[e][j][u] = sigf(go) * tanhf(cn);
                }
            }
        } else if (u < 2048) {
            if (j >= 1) {
                int r = u - 1024;
                float v = dot1024(Wp + (size_t)r * 3072 + 1024, s_a[e][j - 1], lane);
                if (lane == 0) {
                    v = fmaxf(v + s_base[e][r], 0.0f);
                    s_f[e][j - 1][r] = v;
                    float df = v - goal[r];
                    s_diff2[e][j - 1][r] = df * df;
                }
            }
        } else { // u == 2048 : reduce d_{j-2}
            if (j >= 2) {
                int k = j - 2;
                float acc = warp_sum1024(s_diff2[e][k], lane);
                if (lane == 0) s_d[e][k] = acc * (1.0f / 1024.0f);
            }
        }
    }
    // spare warps prefetch rW_ih (needed fully in E2_pre) during expansion 1
    if (e == 0 && j >= 1 && gwid >= 2049) {
        int widx = (gwid - 2049) * 32 + lane;
        const size_t total = (size_t)4096 * 2048 * 4;
        size_t chunk = (total / 10 + 127) & ~(size_t)127;
        size_t beg = (size_t)(j - 1) * chunk;
        size_t len = (beg + chunk <= total) ? chunk : (beg < total ? total - beg : 0);
        if (len) l2_prefetch((const char*)rW_ih + beg, len, widx, (NWARPS - 2049) * 32);
    }
    gridbar();
}

__global__ void __launch_bounds__(NT, 1)
va_kernel(const float* __restrict__ tsn,
          const float* __restrict__ W_fe,  const float* __restrict__ b_fe,
          const float* __restrict__ gW_ih0,const float* __restrict__ gW_ihR,
          const float* __restrict__ gb_ih, const float* __restrict__ gb_hh,
          const float* __restrict__ rW_ih, const float* __restrict__ rW_hh,
          const float* __restrict__ rb_ih, const float* __restrict__ rb_hh,
          const float* __restrict__ Wp,    const float* __restrict__ bp,
          const float* __restrict__ We2a,  const float* __restrict__ be2a,
          const float* __restrict__ We2v,  const float* __restrict__ be2v,
          const float* __restrict__ We2n,  const float* __restrict__ be2n,
          float* __restrict__ out) {
    const int tid  = threadIdx.x;
    const int lane = tid & 31;
    const int gwid = blockIdx.x * WPB + (tid >> 5);
    const int gtid = blockIdx.x * NT + tid;

    // ---------- P0: max-pool partials (rows split across blocks) + rb ----------
    {
        const int r0 = blockIdx.x * 28;
        const int r1 = min(4096, r0 + 28);
        float m0 = -FLT_MAX, m1 = -FLT_MAX;
        for (int r = r0; r < r1; ++r) {
            m0 = fmaxf(m0, tsn[(size_t)r * HD + tid]);
            m1 = fmaxf(m1, tsn[(size_t)r * HD + 512 + tid]);
        }
        s_maxpart[blockIdx.x][tid] = m0;
        s_maxpart[blockIdx.x][tid + 512] = m1;
        for (int i = gtid; i < 4096; i += NB * NT) s_rb[i] = rb_ih[i] + rb_hh[i];
    }
    gridbar();

    // ---------- P1: finish max ----------
    if (gtid < HD) {
        float m = -FLT_MAX;
        for (int b = 0; b < NB; ++b) m = fmaxf(m, s_maxpart[b][gtid]);
        s_maxv[gtid] = m;
    }
    gridbar();

    // ---------- P2: fs = W_fe @ maxv + b_fe (idle warps prefetch Wp) ----------
    if (gwid < HD) {
        float v = dot1024(W_fe + (size_t)gwid * HD, s_maxv, lane);
        if (lane == 0) s_fs[gwid] = v + b_fe[gwid];
    } else {
        int widx = (gwid - 1024) * 32 + lane;
        l2_prefetch(Wp, (size_t)1024 * 3072 * 4, widx, (NWARPS - 1024) * 32);
    }
    gridbar();

    // ---------- P3: goal LSTM layer 0 (c=0 -> skip f-gate) + cur_action ----------
    for (int u = gwid; u < 1024 + 2513; u += NWARPS) {
        if (u < 1024) {
            float di, dg, dog;
            dot3_1024(gW_ih0 + (size_t)u * 2048,
                      gW_ih0 + (size_t)(u + 2048) * 2048,
                      gW_ih0 + (size_t)(u + 3072) * 2048, s_fs, lane, di, dg, dog);
            if (lane == 0) {
                float gi = di  + gb_ih[u] + gb_hh[u];
                float gg = dg  + gb_ih[u + 2048] + gb_hh[u + 2048];
                float go = dog + gb_ih[u + 3072] + gb_hh[u + 3072];
                float cn = sigf(gi) * tanhf(gg);
                s_gh[0][u] = sigf(go) * tanhf(cn);
            }
        } else {
            int r = u - 1024;
            float v = dot1024(We2a + (size_t)r * HD, s_fs, lane);
            if (lane == 0) out[OFF_CA + r] = v + be2a[r];
        }
    }
    gridbar();

    // ---------- P4..P7: goal LSTM layers 1..4 (idle warps prefetch rW_hh) ----------
    for (int l = 1; l <= 4; ++l) {
        const float* Wl = gW_ihR + (size_t)(l - 1) * 4096 * 1024;
        const float* xin = s_gh[l - 1];
        const float* bi = gb_ih + (size_t)l * 4096;
        const float* bh = gb_hh + (size_t)l * 4096;
        if (gwid < 1024) {
            int u = gwid;
            float di, dg, dog;
            dot3_1024(Wl + (size_t)u * HD, Wl + (size_t)(u + 2048) * HD,
                      Wl + (size_t)(u + 3072) * HD, xin, lane, di, dg, dog);
            if (lane == 0) {
                float gi = di  + bi[u] + bh[u];
                float gg = dg  + bi[u + 2048] + bh[u + 2048];
                float go = dog + bi[u + 3072] + bh[u + 3072];
                float cn = sigf(gi) * tanhf(gg);
                s_gh[l][u] = sigf(go) * tanhf(cn);
            }
        } else {
            int widx = (gwid - 1024) * 32 + lane;
            const size_t quarter = (size_t)4096 * 1024;  // bytes (16.7MB / 4)
            l2_prefetch((const char*)rW_hh + (size_t)(l - 1) * quarter, quarter,
                        widx, (NWARPS - 1024) * 32);
        }
        gridbar();
    }
    const float* goal = s_gh[4];

    // ---------- P8: expansion-1 pre (a_in = 0) ----------
    for (int u = gwid; u < 4096 + 1024 + 1; u += NWARPS) {
        if (u < 4096) {
            float v = dot1024(rW_ih + (size_t)u * 2048 + 1024, s_fs, lane);
            if (lane == 0) s_xpart[0][u] = v + s_rb[u];
        } else if (u < 5120) {
            int r = u - 4096;
            float v = dot2x_1024(Wp + (size_t)r * 3072, s_fs,
                                 Wp + (size_t)r * 3072 + 2048, goal, lane);
            if (lane == 0) s_base[0][r] = v + bp[r];
        } else { // bd0
            float acc = 0.0f;
            for (int i = lane; i < HD; i += 32) {
                float df = s_fs[i] - goal[i];
                acc = fmaf(df, df, acc);
            }
            acc = warp_red(acc);
            if (lane == 0) s_bd0 = acc * (1.0f / 1024.0f);
        }
    }
    gridbar();

    // ---------- Expansion 1 (11 phases) ----------
    for (int j = 0; j <= 10; ++j) expand_phase(0, j, rW_hh, Wp, rW_ih, goal, gwid, lane);

    // ---------- E2_pre: pick i_star, build xpart2/base2, emit f2in ----------
    {
        float d9;
        int istar = scan_e1(lane, &d9);
        if (gwid == 0 && lane == 0) s_d[0][9] = d9;
        const float* a2in = s_a[0][istar];
        const float* f2in = s_f[0][istar];
        for (int u = gwid; u < 4096 + 1024 + 1; u += NWARPS) {
            if (u < 4096) {
                float v = dot2x_1024(rW_ih + (size_t)u * 2048, a2in,
                                     rW_ih + (size_t)u * 2048 + 1024, f2in, lane);
                if (lane == 0) s_xpart[1][u] = v + s_rb[u];
            } else if (u < 5120) {
                int r = u - 4096;
                float v = dot2x_1024(Wp + (size_t)r * 3072, f2in,
                                     Wp + (size_t)r * 3072 + 2048, goal, lane);
                if (lane == 0) s_base[1][r] = v + bp[r];
            } else {
                for (int i = lane; i < HD; i += 32) out[OFF_F2 + i] = f2in[i];
            }
        }
    }
    gridbar();

    // ---------- Expansion 2 (11 phases) ----------
    for (int j = 0; j <= 10; ++j) expand_phase(1, j, rW_hh, Wp, rW_ih, goal, gwid, lane);

    // ---------- P_pa: full score scan + top-2, build pa/pfeat/pgoal ----------
    if (gwid < 3) {
        float bd = s_bd0, best = FLT_MAX; int istar = 0;
        float s1[10];
#pragma unroll
        for (int jj = 0; jj < 10; ++jj) {
            float dj = s_d[0][jj];
            s1[jj] = bd - dj;
            if (s1[jj] < best) { best = s1[jj]; istar = jj; }
            if (dj < bd) bd = dj;
        }
        float d2_9 = warp_sum1024(s_diff2[1][9], lane) * (1.0f / 1024.0f);
        float s2[10];
#pragma unroll
        for (int jj = 0; jj < 10; ++jj) {
            float dj = (jj == 9) ? d2_9 : s_d[1][jj];
            s2[jj] = bd - dj;
            if (dj < bd) bd = dj;
        }
        float b0 = FLT_MAX, b1 = FLT_MAX; int i0 = 0, i1 = 0;
#pragma unroll
        for (int k = 0; k < 20; ++k) {
            float v = (k < 10) ? ((k == istar) ? FLT_MAX : s1[k]) : s2[k - 10];
            if (v < b0) { b1 = b0; i1 = i0; b0 = v; i0 = k; }
            else if (v < b1) { b1 = v; i1 = k; }
        }
        if (gwid < 2) {
            int idx = (gwid == 0) ? i0 : i1;
            const float* a2in = s_a[0][istar];
            const float* f2in = s_f[0][istar];
            for (int i = lane; i < HD; i += 32) {
                float pa, pf;
                if (idx < 10) {
                    pa = s_a[0][idx][i] / 2.0f;
                    pf = (s_fs[i] + s_f[0][idx][i]) / 2.0f;
                } else {
                    int jd = idx - 10;
                    pa = (a2in[i] + s_a[1][jd][i]) / 3.0f;
                    pf = (s_fs[i] + f2in[i] + s_f[1][jd][i]) / 3.0f;
                }
                s_pa[gwid][i] = pa;
                out[OFF_PF + gwid * HD + i] = pf;
            }
        } else { // gwid == 2: pgoal
            for (int i = lane; i < HD; i += 32) {
                out[OFF_PG + i] = goal[i];
                out[OFF_PG + HD + i] = goal[i];
            }
        }
    }
    gridbar();

    // ---------- P_pred: final prediction matvecs ----------
    for (int u = gwid; u < 5980; u += NWARPS) {
        const float* W; const float* bias; int i, r, off, rows;
        if (u < 5026)      { i = u / 2513;            r = u % 2513;            W = We2a; bias = be2a; off = OFF_PA; rows = 2513; }
        else if (u < 5276) { int lu = u - 5026; i = lu / 125; r = lu % 125;    W = We2v; bias = be2v; off = OFF_PV; rows = 125; }
        else               { int lu = u - 5276; i = lu / 352; r = lu % 352;    W = We2n; bias = be2n; off = OFF_PN; rows = 352; }
        float v = dot1024(W + (size_t)r * HD, s_pa[i], lane);
        if (lane == 0) out[off + i * rows + r] = v + bias[r];
    }
}

extern "C" void kernel_launch(void* const* d_in, const int* in_sizes, int n_in,
                              void* d_out, int out_size) {
    const float* tsn    = (const float*)d_in[0];
    const float* W_fe   = (const float*)d_in[1];
    const float* b_fe   = (const float*)d_in[2];
    const float* gW_ih0 = (const float*)d_in[3];
    const float* gW_ihR = (const float*)d_in[4];
    // d_in[5] = gW_hh : multiplied by zero hidden state everywhere -> unused
    const float* gb_ih  = (const float*)d_in[6];
    const float* gb_hh  = (const float*)d_in[7];
    const float* rW_ih  = (const float*)d_in[8];
    const float* rW_hh  = (const float*)d_in[9];
    const float* rb_ih  = (const float*)d_in[10];
    const float* rb_hh  = (const float*)d_in[11];
    const float* Wp     = (const float*)d_in[12];
    const float* bp     = (const float*)d_in[13];
    const float* We2a   = (const float*)d_in[14];
    const float* be2a   = (const float*)d_in[15];
    const float* We2v   = (const float*)d_in[16];
    const float* be2v   = (const float*)d_in[17];
    const float* We2n   = (const float*)d_in[18];
    const float* be2n   = (const float*)d_in[19];

    va_kernel<<<NB, NT>>>(tsn, W_fe, b_fe, gW_ih0, gW_ihR, gb_ih, gb_hh,
                          rW_ih, rW_hh, rb_ih, rb_hh, Wp, bp,
                          We2a, be2a, We2v, be2v, We2n, be2n,
                          (float*)d_out);
}

// round 3
// speedup vs baseline: 1.2436x; 1.1674x over previous
#include <cuda_runtime.h>
#include <math.h>
#include <float.h>

#define NB 148
#define NT 512
#define WPB (NT/32)
#define NWARPS (NB*WPB)
#define HD 1024

// ---- output layout (tuple flattened in order) ----
#define OFF_PA 0        // pred_actions [2,2513]
#define OFF_PV 5026     // pred_verbs   [2,125]
#define OFF_PN 5276     // pred_nouns   [2,352]
#define OFF_PF 5980     // pfeat        [2,1024]
#define OFF_PG 8028     // pgoal        [2,1024]
#define OFF_F2 10076    // f2in         [1,1024]
#define OFF_CA 11100    // cur_action   [1,2513]

// ---- scratch (device globals; no allocation allowed) ----
__device__ unsigned s_maxu[HD];                    // zero-init; re-zeroed each call in P3
__device__ __align__(16) float s_fs[HD];
__device__ __align__(16) float s_gh[5][HD];        // goal layer outputs; s_gh[4] = goal
__device__ __align__(16) float s_rb[4*HD];
__device__ __align__(16) float s_xpart[2][4*HD];
__device__ __align__(16) float s_base[2][HD];
__device__ __align__(16) float s_c[HD];
__device__ __align__(16) float s_a[2][10][HD];
__device__ __align__(16) float s_f[2][10][HD];
__device__ __align__(16) float s_diff2[2][10][HD];
__device__ float s_d[2][10];
__device__ float s_bd0;
__device__ __align__(16) float s_pa[2][HD];
__device__ __align__(128) unsigned s_barGen;
__device__ __align__(128) unsigned s_barCnt;

// ---- fast grid barrier: acq/rel atomics, no fences, tight poll ----
__device__ __forceinline__ unsigned ld_acq(unsigned* p) {
    unsigned v;
    asm volatile("ld.acquire.gpu.global.u32 %0, [%1];" : "=r"(v) : "l"(p) : "memory");
    return v;
}
__device__ __forceinline__ void gridbar() {
    __syncthreads();
    if (threadIdx.x == 0) {
        unsigned gen = ld_acq(&s_barGen);
        unsigned old;
        asm volatile("atom.acq_rel.gpu.global.add.u32 %0, [%1], 1;"
                     : "=r"(old) : "l"(&s_barCnt) : "memory");
        if (old == NB - 1) {
            asm volatile("st.relaxed.gpu.global.u32 [%0], 0;" :: "l"(&s_barCnt) : "memory");
            asm volatile("st.release.gpu.global.u32 [%0], %1;"
                         :: "l"(&s_barGen), "r"(gen + 1) : "memory");
        } else {
            while (ld_acq(&s_barGen) == gen) {}
        }
    }
    __syncthreads();
}

__device__ __forceinline__ float sigf(float x) { return 1.0f / (1.0f + expf(-x)); }

__device__ __forceinline__ unsigned encf(float f) {
    unsigned u = __float_as_uint(f);
    return (u & 0x80000000u) ? ~u : (u | 0x80000000u);
}

__device__ __forceinline__ float warp_red(float a) {
#pragma unroll
    for (int o = 16; o; o >>= 1) a += __shfl_xor_sync(0xffffffffu, a, o);
    return a;
}

__device__ __forceinline__ float dot1024(const float* __restrict__ w,
                                         const float* __restrict__ x, int lane) {
    const float4* w4 = (const float4*)w;
    const float4* x4 = (const float4*)x;
    float acc = 0.0f;
#pragma unroll
    for (int i = 0; i < 8; ++i) {
        float4 a = w4[lane + (i << 5)];
        float4 b = x4[lane + (i << 5)];
        acc = fmaf(a.x, b.x, fmaf(a.y, b.y, fmaf(a.z, b.z, fmaf(a.w, b.w, acc))));
    }
    return warp_red(acc);
}

// dot with ordered-uint-encoded x (max-pool result)
__device__ __forceinline__ float dot1024_dec(const float* __restrict__ w,
                                             const unsigned* __restrict__ xu, int lane) {
    const float4* w4 = (const float4*)w;
    const uint4* x4 = (const uint4*)xu;
    float acc = 0.0f;
#pragma unroll
    for (int i = 0; i < 8; ++i) {
        int idx = lane + (i << 5);
        float4 a = w4[idx];
        uint4 k = x4[idx];
        float x0 = __uint_as_float((k.x & 0x80000000u) ? (k.x & 0x7FFFFFFFu) : ~k.x);
        float x1 = __uint_as_float((k.y & 0x80000000u) ? (k.y & 0x7FFFFFFFu) : ~k.y);
        float x2 = __uint_as_float((k.z & 0x80000000u) ? (k.z & 0x7FFFFFFFu) : ~k.z);
        float x3 = __uint_as_float((k.w & 0x80000000u) ? (k.w & 0x7FFFFFFFu) : ~k.w);
        acc = fmaf(a.x, x0, fmaf(a.y, x1, fmaf(a.z, x2, fmaf(a.w, x3, acc))));
    }
    return warp_red(acc);
}

// 4 interleaved 1024-dots: rows w, w+S, w+2S, w+3S against x
__device__ __forceinline__ void dot4_1024(const float* __restrict__ w, size_t S,
                                          const float* __restrict__ x, int lane,
                                          float& r0, float& r1, float& r2, float& r3) {
    const float4* x4 = (const float4*)x;
    float a0 = 0.f, a1 = 0.f, a2 = 0.f, a3 = 0.f;
#pragma unroll
    for (int i = 0; i < 8; ++i) {
        int idx = lane + (i << 5);
        float4 xv = x4[idx];
        float4 w0 = ((const float4*)(w))[idx];
        float4 w1 = ((const float4*)(w + S))[idx];
        float4 w2 = ((const float4*)(w + 2 * S))[idx];
        float4 w3 = ((const float4*)(w + 3 * S))[idx];
        a0 = fmaf(w0.x, xv.x, fmaf(w0.y, xv.y, fmaf(w0.z, xv.z, fmaf(w0.w, xv.w, a0))));
        a1 = fmaf(w1.x, xv.x, fmaf(w1.y, xv.y, fmaf(w1.z, xv.z, fmaf(w1.w, xv.w, a1))));
        a2 = fmaf(w2.x, xv.x, fmaf(w2.y, xv.y, fmaf(w2.z, xv.z, fmaf(w2.w, xv.w, a2))));
        a3 = fmaf(w3.x, xv.x, fmaf(w3.y, xv.y, fmaf(w3.z, xv.z, fmaf(w3.w, xv.w, a3))));
    }
    r0 = warp_red(a0); r1 = warp_red(a1); r2 = warp_red(a2); r3 = warp_red(a3);
}

// 3 interleaved 1024-dots with arbitrary row pointers (goal LSTM: i, g, o gates)
__device__ __forceinline__ void dot3_1024(const float* __restrict__ w0,
                                          const float* __restrict__ w1,
                                          const float* __restrict__ w2,
                                          const float* __restrict__ x, int lane,
                                          float& r0, float& r1, float& r2) {
    const float4* x4 = (const float4*)x;
    float a0 = 0.f, a1 = 0.f, a2 = 0.f;
#pragma unroll
    for (int i = 0; i < 8; ++i) {
        int idx = lane + (i << 5);
        float4 xv = x4[idx];
        float4 v0 = ((const float4*)w0)[idx];
        float4 v1 = ((const float4*)w1)[idx];
        float4 v2 = ((const float4*)w2)[idx];
        a0 = fmaf(v0.x, xv.x, fmaf(v0.y, xv.y, fmaf(v0.z, xv.z, fmaf(v0.w, xv.w, a0))));
        a1 = fmaf(v1.x, xv.x, fmaf(v1.y, xv.y, fmaf(v1.z, xv.z, fmaf(v1.w, xv.w, a1))));
        a2 = fmaf(v2.x, xv.x, fmaf(v2.y, xv.y, fmaf(v2.z, xv.z, fmaf(v2.w, xv.w, a2))));
    }
    r0 = warp_red(a0); r1 = warp_red(a1); r2 = warp_red(a2);
}

// two interleaved 1024-dots with different x vectors, summed (concat dots)
__device__ __forceinline__ float dot2x_1024(const float* __restrict__ wa,
                                            const float* __restrict__ xa,
                                            const float* __restrict__ wb,
                                            const float* __restrict__ xb, int lane) {
    float a0 = 0.f, a1 = 0.f;
#pragma unroll
    for (int i = 0; i < 8; ++i) {
        int idx = lane + (i << 5);
        float4 va = ((const float4*)wa)[idx];
        float4 ua = ((const float4*)xa)[idx];
        float4 vb = ((const float4*)wb)[idx];
        float4 ub = ((const float4*)xb)[idx];
        a0 = fmaf(va.x, ua.x, fmaf(va.y, ua.y, fmaf(va.z, ua.z, fmaf(va.w, ua.w, a0))));
        a1 = fmaf(vb.x, ub.x, fmaf(vb.y, ub.y, fmaf(vb.z, ub.z, fmaf(vb.w, ub.w, a1))));
    }
    return warp_red(a0 + a1);
}

__device__ __forceinline__ float warp_sum1024(const float* __restrict__ v, int lane) {
    float acc = 0.0f;
#pragma unroll
    for (int i = 0; i < 32; ++i) acc += v[lane + (i << 5)];
    return warp_red(acc);
}

__device__ __forceinline__ void pf(const void* base, size_t bytes, int widx, int nth) {
    const char* p = (const char*)base;
    for (size_t off = (size_t)widx * 128; off < bytes; off += (size_t)nth * 128)
        asm volatile("prefetch.global.L2 [%0];" :: "l"(p + off));
}

// one step-phase of an expansion, j = 1..10: h_j (j<10), nf_{j-1}, d_{j-2} (j>=2)
__device__ void expand_phase(int e, int j,
                             const float* __restrict__ rW_hh,
                             const float* __restrict__ Wp,
                             const float* __restrict__ We2a,
                             const float* __restrict__ We2v,
                             const float* __restrict__ We2n,
                             const float* __restrict__ goal,
                             int gwid, int lane) {
    for (int u = gwid; u < 2049; u += NWARPS) {
        if (u < 1024) {
            if (j < 10) {
                float di, dfg, dg, dog;
                dot4_1024(rW_hh + (size_t)u * HD, (size_t)1024 * 1024,
                          s_a[e][j - 1], lane, di, dfg, dg, dog);
                if (lane == 0) {
                    float gi = di  + s_xpart[e][u];
                    float gf = dfg + s_xpart[e][u + 1024];
                    float gg = dg  + s_xpart[e][u + 2048];
                    float go = dog + s_xpart[e][u + 3072];
                    float cn = sigf(gi) * tanhf(gg) + sigf(gf) * s_c[u];
                    s_c[u] = cn;
                    s_a[e][j][u] = sigf(go) * tanhf(cn);
                }
            }
        } else if (u < 2048) {
            int r = u - 1024;
            float v = dot1024(Wp + (size_t)r * 3072 + 1024, s_a[e][j - 1], lane);
            if (lane == 0) {
                v = fmaxf(v + s_base[e][r], 0.0f);
                s_f[e][j - 1][r] = v;
                float df = v - goal[r];
                s_diff2[e][j - 1][r] = df * df;
            }
        } else { // u == 2048 : reduce d_{j-2}
            if (j >= 2) {
                int k = j - 2;
                float acc = warp_sum1024(s_diff2[e][k], lane);
                if (lane == 0) s_d[e][k] = acc * (1.0f / 1024.0f);
            }
        }
    }
    // E2 idle warps re-prefetch the prediction heads for P_pred
    if (e == 1 && j >= 6 && gwid >= 2049) {
        int widx = (gwid - 2049) * 32 + lane;
        int nth = (NWARPS - 2049) * 32;
        int seg = j - 6;                     // 0..4
        if (seg < 4) pf((const char*)We2a + (size_t)seg * 2573312, 2573312, widx, nth);
        else { pf(We2v, 125 * 4096, widx, nth); pf(We2n, 352 * 4096, widx, nth); }
    }
    gridbar();
}

__global__ void __launch_bounds__(NT, 1)
va_kernel(const float* __restrict__ tsn,
          const float* __restrict__ W_fe,  const float* __restrict__ b_fe,
          const float* __restrict__ gW_ih0,const float* __restrict__ gW_ihR,
          const float* __restrict__ gb_ih, const float* __restrict__ gb_hh,
          const float* __restrict__ rW_ih, const float* __restrict__ rW_hh,
          const float* __restrict__ rb_ih, const float* __restrict__ rb_hh,
          const float* __restrict__ Wp,    const float* __restrict__ bp,
          const float* __restrict__ We2a,  const float* __restrict__ be2a,
          const float* __restrict__ We2v,  const float* __restrict__ be2v,
          const float* __restrict__ We2n,  const float* __restrict__ be2n,
          float* __restrict__ out) {
    const int tid  = threadIdx.x;
    const int lane = tid & 31;
    const int gwid = blockIdx.x * WPB + (tid >> 5);
    const int gtid = blockIdx.x * NT + tid;

    // ---------- P0: max-pool via ordered-uint REDG + rb + prefetch(W_fe, gW_ih0) ----------
    {
        const int r0 = blockIdx.x * 28;
        const int r1 = min(4096, r0 + 28);
        float m0 = -FLT_MAX, m1 = -FLT_MAX;
        for (int r = r0; r < r1; ++r) {
            m0 = fmaxf(m0, tsn[(size_t)r * HD + tid]);
            m1 = fmaxf(m1, tsn[(size_t)r * HD + 512 + tid]);
        }
        if (r1 > r0) {
            atomicMax(&s_maxu[tid], encf(m0));
            atomicMax(&s_maxu[tid + 512], encf(m1));
        }
        for (int i = gtid; i < 4096; i += NB * NT) s_rb[i] = rb_ih[i] + rb_hh[i];
        pf(W_fe, (size_t)HD * HD * 4, gtid, NB * NT);
        pf(gW_ih0, (size_t)1024 * 2048 * 4, gtid, NB * NT);                       // i rows
        pf(gW_ih0 + (size_t)2048 * 2048, (size_t)2048 * 2048 * 4, gtid, NB * NT); // g,o rows
    }
    gridbar();

    // ---------- P2: fs = W_fe @ maxv + b_fe; idle warps prefetch We2a + gW_ihR L1 ----------
    if (gwid < HD) {
        float v = dot1024_dec(W_fe + (size_t)gwid * HD, s_maxu, lane);
        if (lane == 0) s_fs[gwid] = v + b_fe[gwid];
    } else {
        int widx = (gwid - 1024) * 32 + lane;
        int nth = (NWARPS - 1024) * 32;
        pf(We2a, (size_t)2513 * HD * 4, widx, nth);
        pf(gW_ihR, (size_t)1024 * 1024 * 4, widx, nth);
        pf(gW_ihR + (size_t)2048 * 1024, (size_t)2048 * 1024 * 4, widx, nth);
    }
    gridbar();

    // ---------- P3: goal LSTM layer 0 (c=0); idle warps prefetch gW_ihR L2-4; re-zero maxu ----------
    if (gtid < HD) s_maxu[gtid] = 0;   // reset for next call (consumed in P2)
    if (gwid < 1024) {
        int u = gwid;
        float di, dg, dog;
        dot3_1024(gW_ih0 + (size_t)u * 2048,
                  gW_ih0 + (size_t)(u + 2048) * 2048,
                  gW_ih0 + (size_t)(u + 3072) * 2048, s_fs, lane, di, dg, dog);
        if (lane == 0) {
            float gi = di  + gb_ih[u] + gb_hh[u];
            float gg = dg  + gb_ih[u + 2048] + gb_hh[u + 2048];
            float go = dog + gb_ih[u + 3072] + gb_hh[u + 3072];
            float cn = sigf(gi) * tanhf(gg);
            s_gh[0][u] = sigf(go) * tanhf(cn);
        }
    } else {
        int widx = (gwid - 1024) * 32 + lane;
        int nth = (NWARPS - 1024) * 32;
#pragma unroll
        for (int k = 1; k <= 3; ++k) {
            const float* base = gW_ihR + (size_t)k * 4096 * 1024;
            pf(base, (size_t)1024 * 1024 * 4, widx, nth);
            pf(base + (size_t)2048 * 1024, (size_t)2048 * 1024 * 4, widx, nth);
        }
    }
    gridbar();

    // ---------- P4..P7: goal layers 1..4 + cur_action slices + stream prefetch ----------
    for (int l = 1; l <= 4; ++l) {
        const float* Wl = gW_ihR + (size_t)(l - 1) * 4096 * 1024;
        const float* xin = s_gh[l - 1];
        const float* bi = gb_ih + (size_t)l * 4096;
        const float* bh = gb_hh + (size_t)l * 4096;
        if (gwid < 1024) {
            int u = gwid;
            float di, dg, dog;
            dot3_1024(Wl + (size_t)u * HD, Wl + (size_t)(u + 2048) * HD,
                      Wl + (size_t)(u + 3072) * HD, xin, lane, di, dg, dog);
            if (lane == 0) {
                float gi = di  + bi[u] + bh[u];
                float gg = dg  + bi[u + 2048] + bh[u + 2048];
                float go = dog + bi[u + 3072] + bh[u + 3072];
                float cn = sigf(gi) * tanhf(gg);
                s_gh[l][u] = sigf(go) * tanhf(cn);
            }
        } else if (gwid < 1653) {
            int r = (l - 1) * 629 + (gwid - 1024);
            if (r < 2513) {
                float v = dot1024(We2a + (size_t)r * HD, s_fs, lane);
                if (lane == 0) out[OFF_CA + r] = v + be2a[r];
            }
        } else {
            int widx = (gwid - 1653) * 32 + lane;
            int nth = (NWARPS - 1653) * 32;
            if (l == 1)      pf(rW_ih, (size_t)2048 * 2048 * 4, widx, nth);
            else if (l == 2) pf(rW_ih + (size_t)2048 * 2048, (size_t)2048 * 2048 * 4, widx, nth);
            else if (l == 3) pf(Wp, (size_t)1024 * 3072 * 4, widx, nth);
            else             pf(rW_hh, (size_t)4096 * 1024 * 4, widx, nth);
        }
        gridbar();
    }
    const float* goal = s_gh[4];

    // ---------- P8: E1 xpart (+h0,c0 inline), Wp base, bd0 ----------
    for (int u = gwid; u < 2049; u += NWARPS) {
        if (u < 1024) {
            float d0, d1, d2, d3;
            dot4_1024(rW_ih + (size_t)u * 2048 + 1024, (size_t)1024 * 2048,
                      s_fs, lane, d0, d1, d2, d3);
            if (lane == 0) {
                float gi = d0 + s_rb[u];
                float gf = d1 + s_rb[u + 1024];
                float gg = d2 + s_rb[u + 2048];
                float go = d3 + s_rb[u + 3072];
                s_xpart[0][u] = gi;          s_xpart[0][u + 1024] = gf;
                s_xpart[0][u + 2048] = gg;   s_xpart[0][u + 3072] = go;
                float cn = sigf(gi) * tanhf(gg);
                s_c[u] = cn;
                s_a[0][0][u] = sigf(go) * tanhf(cn);
            }
        } else if (u < 2048) {
            int r = u - 1024;
            float v = dot2x_1024(Wp + (size_t)r * 3072, s_fs,
                                 Wp + (size_t)r * 3072 + 2048, goal, lane);
            if (lane == 0) s_base[0][r] = v + bp[r];
        } else {
            float acc = 0.0f;
            for (int i = lane; i < HD; i += 32) {
                float df = s_fs[i] - goal[i];
                acc = fmaf(df, df, acc);
            }
            acc = warp_red(acc);
            if (lane == 0) s_bd0 = acc * (1.0f / 1024.0f);
        }
    }
    gridbar();

    // ---------- Expansion 1 (10 phases, j=1..10) ----------
    for (int j = 1; j <= 10; ++j)
        expand_phase(0, j, rW_hh, Wp, We2a, We2v, We2n, goal, gwid, lane);

    // ---------- E2_pre: istar scan; xpart2 (+h0,c0), base2, f2in ----------
    {
        __shared__ float sh_d9;
        if ((tid >> 5) == 0) {
            float d9 = warp_sum1024(s_diff2[0][9], lane) * (1.0f / 1024.0f);
            if (lane == 0) sh_d9 = d9;
        }
        __syncthreads();
        float d9 = sh_d9;
        float bd = s_bd0, best = FLT_MAX; int istar = 0;
#pragma unroll
        for (int jj = 0; jj < 10; ++jj) {
            float dj = (jj == 9) ? d9 : s_d[0][jj];
            float s = bd - dj;
            if (s < best) { best = s; istar = jj; }
            if (dj < bd) bd = dj;
        }
        if (gwid == 0 && lane == 0) s_d[0][9] = d9;
        const float* a2in = s_a[0][istar];
        const float* f2in = s_f[0][istar];
        for (int u = gwid; u < 2049; u += NWARPS) {
            if (u < 1024) {
                float a0, a1, a2, a3, b0, b1, b2, b3;
                dot4_1024(rW_ih + (size_t)u * 2048, (size_t)1024 * 2048,
                          a2in, lane, a0, a1, a2, a3);
                dot4_1024(rW_ih + (size_t)u * 2048 + 1024, (size_t)1024 * 2048,
                          f2in, lane, b0, b1, b2, b3);
                if (lane == 0) {
                    float gi = a0 + b0 + s_rb[u];
                    float gf = a1 + b1 + s_rb[u + 1024];
                    float gg = a2 + b2 + s_rb[u + 2048];
                    float go = a3 + b3 + s_rb[u + 3072];
                    s_xpart[1][u] = gi;          s_xpart[1][u + 1024] = gf;
                    s_xpart[1][u + 2048] = gg;   s_xpart[1][u + 3072] = go;
                    float cn = sigf(gi) * tanhf(gg);
                    s_c[u] = cn;
                    s_a[1][0][u] = sigf(go) * tanhf(cn);
                }
            } else if (u < 2048) {
                int r = u - 1024;
                float v = dot2x_1024(Wp + (size_t)r * 3072, f2in,
                                     Wp + (size_t)r * 3072 + 2048, goal, lane);
                if (lane == 0) s_base[1][r] = v + bp[r];
            } else {
                for (int i = lane; i < HD; i += 32) out[OFF_F2 + i] = f2in[i];
            }
        }
    }
    gridbar();

    // ---------- Expansion 2 (10 phases) ----------
    for (int j = 1; j <= 10; ++j)
        expand_phase(1, j, rW_hh, Wp, We2a, We2v, We2n, goal, gwid, lane);

    // ---------- P_pa: score scan + top-2; pa/pfeat/pgoal ----------
    if (gwid < 3) {
        float bd = s_bd0, best = FLT_MAX; int istar = 0;
        float s1[10];
#pragma unroll
        for (int jj = 0; jj < 10; ++jj) {
            float dj = s_d[0][jj];
            s1[jj] = bd - dj;
            if (s1[jj] < best) { best = s1[jj]; istar = jj; }
            if (dj < bd) bd = dj;
        }
        float d2_9 = warp_sum1024(s_diff2[1][9], lane) * (1.0f / 1024.0f);
        float s2[10];
#pragma unroll
        for (int jj = 0; jj < 10; ++jj) {
            float dj = (jj == 9) ? d2_9 : s_d[1][jj];
            s2[jj] = bd - dj;
            if (dj < bd) bd = dj;
        }
        float b0 = FLT_MAX, b1 = FLT_MAX; int i0 = 0, i1 = 0;
#pragma unroll
        for (int k = 0; k < 20; ++k) {
            float v = (k < 10) ? ((k == istar) ? FLT_MAX : s1[k]) : s2[k - 10];
            if (v < b0) { b1 = b0; i1 = i0; b0 = v; i0 = k; }
            else if (v < b1) { b1 = v; i1 = k; }
        }
        if (gwid < 2) {
            int idx = (gwid == 0) ? i0 : i1;
            const float* a2in = s_a[0][istar];
            const float* f2in = s_f[0][istar];
            for (int i = lane; i < HD; i += 32) {
                float pa, pfv;
                if (idx < 10) {
                    pa = s_a[0][idx][i] / 2.0f;
                    pfv = (s_fs[i] + s_f[0][idx][i]) / 2.0f;
                } else {
                    int jd = idx - 10;
                    pa = (a2in[i] + s_a[1][jd][i]) / 3.0f;
                    pfv = (s_fs[i] + f2in[i] + s_f[1][jd][i]) / 3.0f;
                }
                s_pa[gwid][i] = pa;
                out[OFF_PF + gwid * HD + i] = pfv;
            }
        } else {
            for (int i = lane; i < HD; i += 32) {
                out[OFF_PG + i] = goal[i];
                out[OFF_PG + HD + i] = goal[i];
            }
        }
    }
    gridbar();

    // ---------- P_pred: final prediction matvecs ----------
    for (int u = gwid; u < 5980; u += NWARPS) {
        const float* W; const float* bias; int i, r, off, rows;
        if (u < 5026)      { i = u / 2513;            r = u % 2513;            W = We2a; bias = be2a; off = OFF_PA; rows = 2513; }
        else if (u < 5276) { int lu = u - 5026; i = lu / 125; r = lu % 125;    W = We2v; bias = be2v; off = OFF_PV; rows = 125; }
        else               { int lu = u - 5276; i = lu / 352; r = lu % 352;    W = We2n; bias = be2n; off = OFF_PN; rows = 352; }
        float v = dot1024(W + (size_t)r * HD, s_pa[i], lane);
        if (lane == 0) out[off + i * rows + r] = v + bias[r];
    }
}

extern "C" void kernel_launch(void* const* d_in, const int* in_sizes, int n_in,
                              void* d_out, int out_size) {
    const float* tsn    = (const float*)d_in[0];
    const float* W_fe   = (const float*)d_in[1];
    const float* b_fe   = (const float*)d_in[2];
    const float* gW_ih0 = (const float*)d_in[3];
    const float* gW_ihR = (const float*)d_in[4];
    // d_in[5] = gW_hh : multiplied by zero hidden state everywhere -> unused
    const float* gb_ih  = (const float*)d_in[6];
    const float* gb_hh  = (const float*)d_in[7];
    const float* rW_ih  = (const float*)d_in[8];
    const float* rW_hh  = (const float*)d_in[9];
    const float* rb_ih  = (const float*)d_in[10];
    const float* rb_hh  = (const float*)d_in[11];
    const float* Wp     = (const float*)d_in[12];
    const float* bp     = (const float*)d_in[13];
    const float* We2a   = (const float*)d_in[14];
    const float* be2a   = (const float*)d_in[15];
    const float* We2v   = (const float*)d_in[16];
    const float* be2v   = (const float*)d_in[17];
    const float* We2n   = (const float*)d_in[18];
    const float* be2n   = (const float*)d_in[19];

    va_kernel<<<NB, NT>>>(tsn, W_fe, b_fe, gW_ih0, gW_ihR, gb_ih, gb_hh,
                          rW_ih, rW_hh, rb_ih, rb_hh, Wp, bp,
                          We2a, be2a, We2v, be2v, We2n, be2n,
                          (float*)d_out);
}

// round 4
// speedup vs baseline: 1.4508x; 1.1666x over previous
#include <cuda_runtime.h>
#include <math.h>
#include <float.h>

#define NB 148
#define NBC 128                 // compute blocks (barrier group)
#define NSB (NB - NBC)          // 20 streamer blocks
#define NT 512
#define WPB (NT/32)
#define NWARPC (NBC*WPB)        // 2048 compute warps
#define HD 1024

// ---- output layout (tuple flattened in order) ----
#define OFF_PA 0        // pred_actions [2,2513]
#define OFF_PV 5026     // pred_verbs   [2,125]
#define OFF_PN 5276     // pred_nouns   [2,352]
#define OFF_PF 5980     // pfeat        [2,1024]
#define OFF_PG 8028     // pgoal        [2,1024]
#define OFF_F2 10076    // f2in         [1,1024]
#define OFF_CA 11100    // cur_action   [1,2513]

// ---- scratch (device globals; no allocation allowed) ----
__device__ unsigned s_maxu[HD];                    // zero-init; re-zeroed each call in P3
__device__ __align__(16) float s_fs[HD];
__device__ __align__(16) float s_gh[5][HD];
__device__ __align__(16) float s_rb[4*HD];
__device__ __align__(16) float s_xpart[2][4*HD];
__device__ __align__(16) float s_base[2][HD];
__device__ __align__(16) float s_c[HD];
__device__ __align__(16) float s_a[2][10][HD];
__device__ __align__(16) float s_f[2][10][HD];
__device__ __align__(16) float s_diff2[2][10][HD];
__device__ float s_d[2][10];
__device__ float s_bd0;
__device__ __align__(128) unsigned s_barGen;       // monotonic across calls
__device__ __align__(128) unsigned s_barCnt;

// ---- fast grid barrier over the NBC compute blocks only ----
__device__ __forceinline__ unsigned ld_acq(unsigned* p) {
    unsigned v;
    asm volatile("ld.acquire.gpu.global.u32 %0, [%1];" : "=r"(v) : "l"(p) : "memory");
    return v;
}
__device__ __forceinline__ unsigned ld_rlx(unsigned* p) {
    unsigned v;
    asm volatile("ld.relaxed.gpu.global.u32 %0, [%1];" : "=r"(v) : "l"(p) : "memory");
    return v;
}
__device__ __forceinline__ void gridbar() {
    __syncthreads();
    if (threadIdx.x == 0) {
        unsigned gen = ld_acq(&s_barGen);
        unsigned old;
        asm volatile("atom.acq_rel.gpu.global.add.u32 %0, [%1], 1;"
                     : "=r"(old) : "l"(&s_barCnt) : "memory");
        if (old == NBC - 1) {
            asm volatile("st.relaxed.gpu.global.u32 [%0], 0;" :: "l"(&s_barCnt) : "memory");
            asm volatile("st.release.gpu.global.u32 [%0], %1;"
                         :: "l"(&s_barGen), "r"(gen + 1) : "memory");
        } else {
            while (ld_acq(&s_barGen) == gen) {}
        }
    }
    __syncthreads();
}

__device__ __forceinline__ float sigf(float x) { return 1.0f / (1.0f + expf(-x)); }

__device__ __forceinline__ unsigned encf(float f) {
    unsigned u = __float_as_uint(f);
    return (u & 0x80000000u) ? ~u : (u | 0x80000000u);
}

__device__ __forceinline__ float warp_red(float a) {
#pragma unroll
    for (int o = 16; o; o >>= 1) a += __shfl_xor_sync(0xffffffffu, a, o);
    return a;
}

__device__ __forceinline__ float dot1024(const float* __restrict__ w,
                                         const float* __restrict__ x, int lane) {
    const float4* w4 = (const float4*)w;
    const float4* x4 = (const float4*)x;
    float acc = 0.0f;
#pragma unroll
    for (int i = 0; i < 8; ++i) {
        float4 a = w4[lane + (i << 5)];
        float4 b = x4[lane + (i << 5)];
        acc = fmaf(a.x, b.x, fmaf(a.y, b.y, fmaf(a.z, b.z, fmaf(a.w, b.w, acc))));
    }
    return warp_red(acc);
}

// dot with ordered-uint-encoded x (max-pool result)
__device__ __forceinline__ float dot1024_dec(const float* __restrict__ w,
                                             const unsigned* __restrict__ xu, int lane) {
    const float4* w4 = (const float4*)w;
    const uint4* x4 = (const uint4*)xu;
    float acc = 0.0f;
#pragma unroll
    for (int i = 0; i < 8; ++i) {
        int idx = lane + (i << 5);
        float4 a = w4[idx];
        uint4 k = x4[idx];
        float x0 = __uint_as_float((k.x & 0x80000000u) ? (k.x & 0x7FFFFFFFu) : ~k.x);
        float x1 = __uint_as_float((k.y & 0x80000000u) ? (k.y & 0x7FFFFFFFu) : ~k.y);
        float x2 = __uint_as_float((k.z & 0x80000000u) ? (k.z & 0x7FFFFFFFu) : ~k.z);
        float x3 = __uint_as_float((k.w & 0x80000000u) ? (k.w & 0x7FFFFFFFu) : ~k.w);
        acc = fmaf(a.x, x0, fmaf(a.y, x1, fmaf(a.z, x2, fmaf(a.w, x3, acc))));
    }
    return warp_red(acc);
}

__device__ __forceinline__ void dot4_1024(const float* __restrict__ w, size_t S,
                                          const float* __restrict__ x, int lane,
                                          float& r0, float& r1, float& r2, float& r3) {
    const float4* x4 = (const float4*)x;
    float a0 = 0.f, a1 = 0.f, a2 = 0.f, a3 = 0.f;
#pragma unroll
    for (int i = 0; i < 8; ++i) {
        int idx = lane + (i << 5);
        float4 xv = x4[idx];
        float4 w0 = ((const float4*)(w))[idx];
        float4 w1 = ((const float4*)(w + S))[idx];
        float4 w2 = ((const float4*)(w + 2 * S))[idx];
        float4 w3 = ((const float4*)(w + 3 * S))[idx];
        a0 = fmaf(w0.x, xv.x, fmaf(w0.y, xv.y, fmaf(w0.z, xv.z, fmaf(w0.w, xv.w, a0))));
        a1 = fmaf(w1.x, xv.x, fmaf(w1.y, xv.y, fmaf(w1.z, xv.z, fmaf(w1.w, xv.w, a1))));
        a2 = fmaf(w2.x, xv.x, fmaf(w2.y, xv.y, fmaf(w2.z, xv.z, fmaf(w2.w, xv.w, a2))));
        a3 = fmaf(w3.x, xv.x, fmaf(w3.y, xv.y, fmaf(w3.z, xv.z, fmaf(w3.w, xv.w, a3))));
    }
    r0 = warp_red(a0); r1 = warp_red(a1); r2 = warp_red(a2); r3 = warp_red(a3);
}

__device__ __forceinline__ void dot3_1024(const float* __restrict__ w0,
                                          const float* __restrict__ w1,
                                          const float* __restrict__ w2,
                                          const float* __restrict__ x, int lane,
                                          float& r0, float& r1, float& r2) {
    const float4* x4 = (const float4*)x;
    float a0 = 0.f, a1 = 0.f, a2 = 0.f;
#pragma unroll
    for (int i = 0; i < 8; ++i) {
        int idx = lane + (i << 5);
        float4 xv = x4[idx];
        float4 v0 = ((const float4*)w0)[idx];
        float4 v1 = ((const float4*)w1)[idx];
        float4 v2 = ((const float4*)w2)[idx];
        a0 = fmaf(v0.x, xv.x, fmaf(v0.y, xv.y, fmaf(v0.z, xv.z, fmaf(v0.w, xv.w, a0))));
        a1 = fmaf(v1.x, xv.x, fmaf(v1.y, xv.y, fmaf(v1.z, xv.z, fmaf(v1.w, xv.w, a1))));
        a2 = fmaf(v2.x, xv.x, fmaf(v2.y, xv.y, fmaf(v2.z, xv.z, fmaf(v2.w, xv.w, a2))));
    }
    r0 = warp_red(a0); r1 = warp_red(a1); r2 = warp_red(a2);
}

__device__ __forceinline__ float dot2x_1024(const float* __restrict__ wa,
                                            const float* __restrict__ xa,
                                            const float* __restrict__ wb,
                                            const float* __restrict__ xb, int lane) {
    float a0 = 0.f, a1 = 0.f;
#pragma unroll
    for (int i = 0; i < 8; ++i) {
        int idx = lane + (i << 5);
        float4 va = ((const float4*)wa)[idx];
        float4 ua = ((const float4*)xa)[idx];
        float4 vb = ((const float4*)wb)[idx];
        float4 ub = ((const float4*)xb)[idx];
        a0 = fmaf(va.x, ua.x, fmaf(va.y, ua.y, fmaf(va.z, ua.z, fmaf(va.w, ua.w, a0))));
        a1 = fmaf(vb.x, ub.x, fmaf(vb.y, ub.y, fmaf(vb.z, ub.z, fmaf(vb.w, ub.w, a1))));
    }
    return warp_red(a0 + a1);
}

__device__ __forceinline__ float warp_sum1024(const float* __restrict__ v, int lane) {
    float acc = 0.0f;
#pragma unroll
    for (int i = 0; i < 32; ++i) acc += v[lane + (i << 5)];
    return warp_red(acc);
}

__device__ __forceinline__ void pf(const void* base, size_t bytes, int widx, int nth) {
    const char* p = (const char*)base;
    for (size_t off = (size_t)widx * 128; off < bytes; off += (size_t)nth * 128)
        asm volatile("prefetch.global.L2 [%0];" :: "l"(p + off));
}

// stream budget (relative gen -> allowed cumulative bytes)
__device__ __forceinline__ size_t budget_of(unsigned g) {
    switch (g) {
        case 0: return 41943040UL;    // W_fe + gW_ih0(i,g,o) + L1
        case 1: return 54525952UL;    // + L2
        case 2: return 67108864UL;    // + L3
        case 3: return 113246208UL;   // + L4 + rW_ih
        case 4: return 125829120UL;   // + Wp
        default: return 142606336UL;  // + rW_hh  (all)
    }
}
#define ST_TOTAL 142606336UL

// one step-phase of an expansion, j = 1..10 (2048 units on 2048 warps)
__device__ void expand_phase(int e, int j,
                             const float* __restrict__ rW_hh,
                             const float* __restrict__ Wp,
                             const float* __restrict__ goal,
                             int gwid, int lane) {
    int u = gwid;
    if (u < 1024) {
        if (j < 10) {
            float di, dfg, dg, dog;
            dot4_1024(rW_hh + (size_t)u * HD, (size_t)1024 * 1024,
                      s_a[e][j - 1], lane, di, dfg, dg, dog);
            if (lane == 0) {
                float gi = di  + s_xpart[e][u];
                float gf = dfg + s_xpart[e][u + 1024];
                float gg = dg  + s_xpart[e][u + 2048];
                float go = dog + s_xpart[e][u + 3072];
                float cn = sigf(gi) * tanhf(gg) + sigf(gf) * s_c[u];
                s_c[u] = cn;
                s_a[e][j][u] = sigf(go) * tanhf(cn);
            }
        }
        if (u == 1023 && j >= 2) {
            int k = j - 2;
            float acc = warp_sum1024(s_diff2[e][k], lane);
            if (lane == 0) s_d[e][k] = acc * (1.0f / 1024.0f);
        }
    } else {
        int r = u - 1024;
        float v = dot1024(Wp + (size_t)r * 3072 + 1024, s_a[e][j - 1], lane);
        if (lane == 0) {
            v = fmaxf(v + s_base[e][r], 0.0f);
            s_f[e][j - 1][r] = v;
            float df = v - goal[r];
            s_diff2[e][j - 1][r] = df * df;
        }
    }
    gridbar();
}

__global__ void __launch_bounds__(NT, 1)
va_kernel(const float* __restrict__ tsn,
          const float* __restrict__ W_fe,  const float* __restrict__ b_fe,
          const float* __restrict__ gW_ih0,const float* __restrict__ gW_ihR,
          const float* __restrict__ gb_ih, const float* __restrict__ gb_hh,
          const float* __restrict__ rW_ih, const float* __restrict__ rW_hh,
          const float* __restrict__ rb_ih, const float* __restrict__ rb_hh,
          const float* __restrict__ Wp,    const float* __restrict__ bp,
          const float* __restrict__ We2a,  const float* __restrict__ be2a,
          const float* __restrict__ We2v,  const float* __restrict__ be2v,
          const float* __restrict__ We2n,  const float* __restrict__ be2n,
          float* __restrict__ out) {
    const int tid  = threadIdx.x;
    const int lane = tid & 31;

    __shared__ float sh_pa[2][HD];
    __shared__ int sh_istar, sh_i0, sh_i1;
    __shared__ float sh_d9;

    // =====================  STREAMER BLOCKS  =====================
    if (blockIdx.x >= NBC) {
        const unsigned g0 = ld_acq(&s_barGen);      // epoch base for this call
        const int sid = (blockIdx.x - NBC) * NT + tid;
        const int nst = NSB * NT;

        // ordered segment table (f-gate rows of goal LSTMs are dead -> skipped)
        const char* segp[14];
        size_t cum[15];
        segp[0]  = (const char*)W_fe;                               cum[0] = 0;
        segp[1]  = (const char*)gW_ih0;                             cum[1] = 4194304;
        segp[2]  = (const char*)(gW_ih0 + (size_t)2048 * 2048);     cum[2] = 12582912;
        cum[3] = 29360128;
#pragma unroll
        for (int l = 0; l < 4; ++l) {
            segp[3 + 2 * l] = (const char*)(gW_ihR + (size_t)l * 4096 * 1024);
            segp[4 + 2 * l] = (const char*)(gW_ihR + (size_t)l * 4096 * 1024 + (size_t)2048 * 1024);
            cum[4 + 2 * l] = cum[3 + 2 * l] + 4194304;
            cum[5 + 2 * l] = cum[4 + 2 * l] + 8388608;
        }
        segp[11] = (const char*)rW_ih;  cum[12] = cum[11] + 33554432;
        segp[12] = (const char*)Wp;     cum[13] = cum[12] + 12582912;
        segp[13] = (const char*)rW_hh;  cum[14] = cum[13] + 16777216;

        int seg = 0;
        for (size_t off = (size_t)sid * 128; off < ST_TOTAL; off += (size_t)nst * 128) {
            while (off >= budget_of(ld_rlx(&s_barGen) - g0)) __nanosleep(128);
            while (off >= cum[seg + 1]) ++seg;
            asm volatile("prefetch.global.L2 [%0];" :: "l"(segp[seg] + (off - cum[seg])));
        }

        // cur_action = fs @ We2a^T + be2a  (fs ready once gen >= g0+2)
        while (ld_acq(&s_barGen) - g0 < 2) __nanosleep(128);
        const int swid = (blockIdx.x - NBC) * WPB + (tid >> 5);
        for (int r = swid; r < 2513; r += NSB * WPB) {
            float v = dot1024(We2a + (size_t)r * HD, s_fs, lane);
            if (lane == 0) out[OFF_CA + r] = v + be2a[r];
        }
        // warm the small heads for P_pred
        pf(We2v, 125 * 4096, sid, nst);
        pf(We2n, 352 * 4096, sid, nst);
        return;
    }

    // =====================  COMPUTE BLOCKS  =====================
    const int gwid = blockIdx.x * WPB + (tid >> 5);     // 0..2047
    const int gtid = blockIdx.x * NT + tid;             // 0..65535

    // ---------- P0: max-pool (ordered-uint REDG) + rb ----------
    {
        const int r0 = blockIdx.x * 32;
        float m0 = -FLT_MAX, m1 = -FLT_MAX;
        for (int r = r0; r < r0 + 32; ++r) {
            m0 = fmaxf(m0, tsn[(size_t)r * HD + tid]);
            m1 = fmaxf(m1, tsn[(size_t)r * HD + 512 + tid]);
        }
        atomicMax(&s_maxu[tid], encf(m0));
        atomicMax(&s_maxu[tid + 512], encf(m1));
        for (int i = gtid; i < 4096; i += NBC * NT) s_rb[i] = rb_ih[i] + rb_hh[i];
    }
    gridbar();   // gen -> g0+1

    // ---------- P2: fs = W_fe @ maxv + b_fe ----------
    if (gwid < HD) {
        float v = dot1024_dec(W_fe + (size_t)gwid * HD, s_maxu, lane);
        if (lane == 0) s_fs[gwid] = v + b_fe[gwid];
    }
    gridbar();   // g0+2  (fs published for streamers)

    // ---------- P3: goal LSTM layer 0 (c=0, f-gate dead); re-zero maxu ----------
    if (gtid < HD) s_maxu[gtid] = 0;
    if (gwid < 1024) {
        int u = gwid;
        float di, dg, dog;
        dot3_1024(gW_ih0 + (size_t)u * 2048,
                  gW_ih0 + (size_t)(u + 2048) * 2048,
                  gW_ih0 + (size_t)(u + 3072) * 2048, s_fs, lane, di, dg, dog);
        if (lane == 0) {
            float gi = di  + gb_ih[u] + gb_hh[u];
            float gg = dg  + gb_ih[u + 2048] + gb_hh[u + 2048];
            float go = dog + gb_ih[u + 3072] + gb_hh[u + 3072];
            float cn = sigf(gi) * tanhf(gg);
            s_gh[0][u] = sigf(go) * tanhf(cn);
        }
    }
    gridbar();

    // ---------- P4..P7: goal layers 1..4 ----------
    for (int l = 1; l <= 4; ++l) {
        const float* Wl = gW_ihR + (size_t)(l - 1) * 4096 * 1024;
        const float* xin = s_gh[l - 1];
        const float* bi = gb_ih + (size_t)l * 4096;
        const float* bh = gb_hh + (size_t)l * 4096;
        if (gwid < 1024) {
            int u = gwid;
            float di, dg, dog;
            dot3_1024(Wl + (size_t)u * HD, Wl + (size_t)(u + 2048) * HD,
                      Wl + (size_t)(u + 3072) * HD, xin, lane, di, dg, dog);
            if (lane == 0) {
                float gi = di  + bi[u] + bh[u];
                float gg = dg  + bi[u + 2048] + bh[u + 2048];
                float go = dog + bi[u + 3072] + bh[u + 3072];
                float cn = sigf(gi) * tanhf(gg);
                s_gh[l][u] = sigf(go) * tanhf(cn);
            }
        }
        gridbar();
    }
    const float* goal = s_gh[4];

    // ---------- P8: E1 xpart (+h0,c0 inline), Wp base, bd0 ----------
    for (int u = gwid; u < 2049; u += NWARPC) {
        if (u < 1024) {
            float d0, d1, d2, d3;
            dot4_1024(rW_ih + (size_t)u * 2048 + 1024, (size_t)1024 * 2048,
                      s_fs, lane, d0, d1, d2, d3);
            if (lane == 0) {
                float gi = d0 + s_rb[u];
                float gf = d1 + s_rb[u + 1024];
                float gg = d2 + s_rb[u + 2048];
                float go = d3 + s_rb[u + 3072];
                s_xpart[0][u] = gi;          s_xpart[0][u + 1024] = gf;
                s_xpart[0][u + 2048] = gg;   s_xpart[0][u + 3072] = go;
                float cn = sigf(gi) * tanhf(gg);
                s_c[u] = cn;
                s_a[0][0][u] = sigf(go) * tanhf(cn);
            }
        } else if (u < 2048) {
            int r = u - 1024;
            float v = dot2x_1024(Wp + (size_t)r * 3072, s_fs,
                                 Wp + (size_t)r * 3072 + 2048, goal, lane);
            if (lane == 0) s_base[0][r] = v + bp[r];
        } else {
            float acc = 0.0f;
            for (int i = lane; i < HD; i += 32) {
                float df = s_fs[i] - goal[i];
                acc = fmaf(df, df, acc);
            }
            acc = warp_red(acc);
            if (lane == 0) s_bd0 = acc * (1.0f / 1024.0f);
        }
    }
    gridbar();

    // ---------- Expansion 1 (10 phases, j=1..10) ----------
    for (int j = 1; j <= 10; ++j) expand_phase(0, j, rW_hh, Wp, goal, gwid, lane);

    // ---------- E2_preA: istar (per block), flattened xpart2/base2, f2in ----------
    {
        if ((tid >> 5) == 0) {
            float d9 = warp_sum1024(s_diff2[0][9], lane) * (1.0f / 1024.0f);
            if (lane == 0) {
                float bd = s_bd0, best = FLT_MAX; int istar = 0;
#pragma unroll
                for (int jj = 0; jj < 10; ++jj) {
                    float dj = (jj == 9) ? d9 : s_d[0][jj];
                    float s = bd - dj;
                    if (s < best) { best = s; istar = jj; }
                    if (dj < bd) bd = dj;
                }
                sh_istar = istar;
                sh_d9 = d9;
            }
        }
        __syncthreads();
        const int istar = sh_istar;
        if (blockIdx.x == 0 && tid == 0) s_d[0][9] = sh_d9;
        const float* a2in = s_a[0][istar];
        const float* f2in = s_f[0][istar];
        for (int u = gwid; u < 5121; u += NWARPC) {
            if (u < 4096) {
                float v = dot2x_1024(rW_ih + (size_t)u * 2048, a2in,
                                     rW_ih + (size_t)u * 2048 + 1024, f2in, lane);
                if (lane == 0) s_xpart[1][u] = v + s_rb[u];
            } else if (u < 5120) {
                int r = u - 4096;
                float v = dot2x_1024(Wp + (size_t)r * 3072, f2in,
                                     Wp + (size_t)r * 3072 + 2048, goal, lane);
                if (lane == 0) s_base[1][r] = v + bp[r];
            } else {
                for (int i = lane; i < HD; i += 32) out[OFF_F2 + i] = f2in[i];
            }
        }
    }
    gridbar();

    // ---------- E2_preB: h0/c0 for expansion 2 (elementwise) ----------
    if (gwid < 32) {
        int row = (gwid << 5) + lane;
        float gi = s_xpart[1][row];
        float gf = s_xpart[1][row + 1024];
        float gg = s_xpart[1][row + 2048];
        float go = s_xpart[1][row + 3072];
        float cn = sigf(gi) * tanhf(gg);
        (void)gf;   // c=0 at step 0: f-gate contributes nothing
        s_c[row] = cn;
        s_a[1][0][row] = sigf(go) * tanhf(cn);
    }
    gridbar();

    // ---------- Expansion 2 (10 phases) ----------
    for (int j = 1; j <= 10; ++j) expand_phase(1, j, rW_hh, Wp, goal, gwid, lane);

    // ---------- Final phase: per-block scan + P_pred (no more barriers) ----------
    {
        if ((tid >> 5) == 0) {
            float d2_9 = warp_sum1024(s_diff2[1][9], lane) * (1.0f / 1024.0f);
            if (lane == 0) {
                float bd = s_bd0, best = FLT_MAX; int istar = 0;
                float s1[10], s2[10];
#pragma unroll
                for (int jj = 0; jj < 10; ++jj) {
                    float dj = s_d[0][jj];
                    s1[jj] = bd - dj;
                    if (s1[jj] < best) { best = s1[jj]; istar = jj; }
                    if (dj < bd) bd = dj;
                }
#pragma unroll
                for (int jj = 0; jj < 10; ++jj) {
                    float dj = (jj == 9) ? d2_9 : s_d[1][jj];
                    s2[jj] = bd - dj;
                    if (dj < bd) bd = dj;
                }
                float b0 = FLT_MAX, b1 = FLT_MAX; int i0 = 0, i1 = 0;
#pragma unroll
                for (int k = 0; k < 20; ++k) {
                    float v = (k < 10) ? ((k == istar) ? FLT_MAX : s1[k]) : s2[k - 10];
                    if (v < b0) { b1 = b0; i1 = i0; b0 = v; i0 = k; }
                    else if (v < b1) { b1 = v; i1 = k; }
                }
                sh_istar = istar; sh_i0 = i0; sh_i1 = i1;
            }
        }
        __syncthreads();
        const int istar = sh_istar;
        const float* a2in = s_a[0][istar];
        const float* f2in = s_f[0][istar];

        for (int t = tid; t < 2048; t += NT) {
            int which = t >> 10;
            int col = t & 1023;
            int idx = which ? sh_i1 : sh_i0;
            float pa;
            if (idx < 10) pa = s_a[0][idx][col] * 0.5f;
            else          pa = (a2in[col] + s_a[1][idx - 10][col]) * (1.0f / 3.0f);
            sh_pa[which][col] = pa;
        }
        if (blockIdx.x == 0) {
            for (int t = tid; t < 2048; t += NT) {
                int which = t >> 10;
                int col = t & 1023;
                int idx = which ? sh_i1 : sh_i0;
                float pfv;
                if (idx < 10) pfv = (s_fs[col] + s_f[0][idx][col]) * 0.5f;
                else          pfv = (s_fs[col] + f2in[col] + s_f[1][idx - 10][col]) * (1.0f / 3.0f);
                out[OFF_PF + which * HD + col] = pfv;
                out[OFF_PG + which * HD + col] = goal[col];
            }
        }
        __syncthreads();

        for (int u = gwid; u < 5980; u += NWARPC) {
            const float* W; const float* bias; int i, r, off, rows;
            if (u < 5026)      { i = u / 2513;          r = u % 2513;         W = We2a; bias = be2a; off = OFF_PA; rows = 2513; }
            else if (u < 5276) { int lu = u - 5026; i = lu / 125; r = lu % 125; W = We2v; bias = be2v; off = OFF_PV; rows = 125; }
            else               { int lu = u - 5276; i = lu / 352; r = lu % 352; W = We2n; bias = be2n; off = OFF_PN; rows = 352; }
            float v = dot1024(W + (size_t)r * HD, sh_pa[i], lane);
            if (lane == 0) out[off + i * rows + r] = v + bias[r];
        }
    }
}

extern "C" void kernel_launch(void* const* d_in, const int* in_sizes, int n_in,
                              void* d_out, int out_size) {
    const float* tsn    = (const float*)d_in[0];
    const float* W_fe   = (const float*)d_in[1];
    const float* b_fe   = (const float*)d_in[2];
    const float* gW_ih0 = (const float*)d_in[3];
    const float* gW_ihR = (const float*)d_in[4];
    // d_in[5] = gW_hh : multiplied by zero hidden state everywhere -> unused
    const float* gb_ih  = (const float*)d_in[6];
    const float* gb_hh  = (const float*)d_in[7];
    const float* rW_ih  = (const float*)d_in[8];
    const float* rW_hh  = (const float*)d_in[9];
    const float* rb_ih  = (const float*)d_in[10];
    const float* rb_hh  = (const float*)d_in[11];
    const float* Wp     = (const float*)d_in[12];
    const float* bp     = (const float*)d_in[13];
    const float* We2a   = (const float*)d_in[14];
    const float* be2a   = (const float*)d_in[15];
    const float* We2v   = (const float*)d_in[16];
    const float* be2v   = (const float*)d_in[17];
    const float* We2n   = (const float*)d_in[18];
    const float* be2n   = (const float*)d_in[19];

    va_kernel<<<NB, NT>>>(tsn, W_fe, b_fe, gW_ih0, gW_ihR, gb_ih, gb_hh,
                          rW_ih, rW_hh, rb_ih, rb_hh, Wp, bp,
                          We2a, be2a, We2v, be2v, We2n, be2n,
                          (float*)d_out);
}

// round 5
// speedup vs baseline: 1.7131x; 1.1808x over previous
#include <cuda_runtime.h>
#include <math.h>
#include <float.h>

#define NB 148
#define NBC 128                 // compute blocks (barrier group)
#define NSB (NB - NBC)          // 20 streamer blocks
#define NT 512
#define WPB (NT/32)
#define NWARPC (NBC*WPB)        // 2048 compute warps
#define HD 1024

// ---- output layout (tuple flattened in order) ----
#define OFF_PA 0        // pred_actions [2,2513]
#define OFF_PV 5026     // pred_verbs   [2,125]
#define OFF_PN 5276     // pred_nouns   [2,352]
#define OFF_PF 5980     // pfeat        [2,1024]
#define OFF_PG 8028     // pgoal        [2,1024]
#define OFF_F2 10076    // f2in         [1,1024]
#define OFF_CA 11100    // cur_action   [1,2513]

// ---- scratch (device globals; no allocation allowed) ----
__device__ unsigned s_maxu[HD];                    // zero-init; re-zeroed each call
__device__ __align__(16) float s_fs[HD];
__device__ __align__(16) float s_gh[5][HD];
__device__ __align__(16) float s_rb[4*HD];
__device__ __align__(16) float s_xpart[2][4*HD];
__device__ __align__(16) float s_base[2][HD];
__device__ __align__(16) float s_c[HD];
__device__ __align__(16) float s_a[2][10][HD];
__device__ __align__(16) float s_f[2][10][HD];
__device__ __align__(16) float s_diff2[2][10][HD];
__device__ float s_d[2][10];
__device__ float s_bd0;
__device__ __align__(128) unsigned long long s_cnt;   // monotonic barrier counter

// ---- monotonic grid barrier over NBC compute blocks ----
__device__ __forceinline__ void gridbar(unsigned long long base, int k) {
    __syncthreads();
    if (threadIdx.x == 0) {
        asm volatile("red.release.gpu.global.add.u64 [%0], 1;" :: "l"(&s_cnt) : "memory");
        const unsigned long long target = base + (unsigned long long)k * NBC;
        unsigned long long v;
        do {
            asm volatile("ld.acquire.gpu.global.u64 %0, [%1];" : "=l"(v) : "l"(&s_cnt) : "memory");
        } while (v < target);
    }
    __syncthreads();
}

__device__ __forceinline__ float sigf(float x) { return 1.0f / (1.0f + expf(-x)); }

__device__ __forceinline__ unsigned encf(float f) {
    unsigned u = __float_as_uint(f);
    return (u & 0x80000000u) ? ~u : (u | 0x80000000u);
}

__device__ __forceinline__ float warp_red(float a) {
#pragma unroll
    for (int o = 16; o; o >>= 1) a += __shfl_xor_sync(0xffffffffu, a, o);
    return a;
}

// half-dot (512 cols) with preloaded x fragment
__device__ __forceinline__ float dot512r(const float4* __restrict__ w4,
                                         const float4 xv[4], int lane) {
    float acc = 0.0f;
#pragma unroll
    for (int i = 0; i < 4; ++i) {
        float4 a = w4[lane + (i << 5)];
        acc = fmaf(a.x, xv[i].x, fmaf(a.y, xv[i].y, fmaf(a.z, xv[i].z, fmaf(a.w, xv[i].w, acc))));
    }
    return warp_red(acc);
}

// full 1024-dot, x from (shared) pointer
__device__ __forceinline__ float dot1024_sm(const float* __restrict__ w,
                                            const float* xs, int lane) {
    float acc = 0.0f;
#pragma unroll
    for (int i = 0; i < 8; ++i) {
        int idx = lane + (i << 5);
        float4 a = ((const float4*)w)[idx];
        float4 b = ((const float4*)xs)[idx];
        acc = fmaf(a.x, b.x, fmaf(a.y, b.y, fmaf(a.z, b.z, fmaf(a.w, b.w, acc))));
    }
    return warp_red(acc);
}

// full 1024-dot, global x
__device__ __forceinline__ float dot1024(const float* __restrict__ w,
                                         const float* __restrict__ x, int lane) {
    float acc = 0.0f;
#pragma unroll
    for (int i = 0; i < 8; ++i) {
        int idx = lane + (i << 5);
        float4 a = ((const float4*)w)[idx];
        float4 b = ((const float4*)x)[idx];
        acc = fmaf(a.x, b.x, fmaf(a.y, b.y, fmaf(a.z, b.z, fmaf(a.w, b.w, acc))));
    }
    return warp_red(acc);
}

__device__ __forceinline__ float warp_sum1024(const float* __restrict__ v, int lane) {
    float acc = 0.0f;
#pragma unroll
    for (int i = 0; i < 32; ++i) acc += v[lane + (i << 5)];
    return warp_red(acc);
}

__device__ __forceinline__ void pf(const void* base, size_t bytes, int idx, int nth) {
    const char* p = (const char*)base;
    for (size_t off = (size_t)idx * 128; off < bytes; off += (size_t)nth * 128)
        asm volatile("prefetch.global.L2 [%0];" :: "l"(p + off));
}

// ---- one expansion step-phase (all 2048 warps busy; 8 rows+8 Wp rows per block) ----
__device__ void expand_phase(int e, int j,
                             const float* __restrict__ rW_hh,
                             const float* __restrict__ Wp,
                             const float* __restrict__ goal,
                             int bid, int wib, int lane, int tid,
                             float* sh_x, float (*sh_part)[6],
                             unsigned long long barbase, int bark) {
    if (tid < 256) ((float4*)sh_x)[tid] = ((const float4*)s_a[e][j - 1])[tid];
    __syncthreads();
    const int slot = wib & 7, half = wib >> 3;
    const int u = bid * 8 + slot;
    const size_t co = (size_t)half * 512;
    float4 xv[4];
    {
        const float4* xs4 = (const float4*)(sh_x + co);
#pragma unroll
        for (int i = 0; i < 4; ++i) xv[i] = xs4[lane + (i << 5)];
    }
    float p0 = 0.f, p1 = 0.f, p2 = 0.f, p3 = 0.f;
    if (j < 10) {
        const float* wr = rW_hh + (size_t)u * HD + co;
        p0 = dot512r((const float4*)wr, xv, lane);
        p1 = dot512r((const float4*)(wr + (size_t)1024 * 1024), xv, lane);
        p2 = dot512r((const float4*)(wr + (size_t)2048 * 1024), xv, lane);
        p3 = dot512r((const float4*)(wr + (size_t)3072 * 1024), xv, lane);
    }
    float p4 = dot512r((const float4*)(Wp + (size_t)u * 3072 + 1024 + co), xv, lane);
    if (lane == 0) {
        sh_part[wib][0] = p0; sh_part[wib][1] = p1; sh_part[wib][2] = p2;
        sh_part[wib][3] = p3; sh_part[wib][4] = p4;
    }
    if (j >= 2 && bid == 0 && wib == 15) {   // global d_{j-2} reduce
        float acc = warp_sum1024(s_diff2[e][j - 2], lane);
        if (lane == 0) s_d[e][j - 2] = acc * (1.0f / 1024.0f);
    }
    __syncthreads();
    if (wib == 0 && lane < 8) {
        int uu = bid * 8 + lane;
        float pw = sh_part[lane][4] + sh_part[lane + 8][4];
        float v = fmaxf(pw + s_base[e][uu], 0.0f);
        s_f[e][j - 1][uu] = v;
        float df = v - goal[uu];
        s_diff2[e][j - 1][uu] = df * df;
        if (j < 10) {
            float gi = sh_part[lane][0] + sh_part[lane + 8][0] + s_xpart[e][uu];
            float gf = sh_part[lane][1] + sh_part[lane + 8][1] + s_xpart[e][uu + 1024];
            float gg = sh_part[lane][2] + sh_part[lane + 8][2] + s_xpart[e][uu + 2048];
            float go = sh_part[lane][3] + sh_part[lane + 8][3] + s_xpart[e][uu + 3072];
            float cn = sigf(gi) * tanhf(gg) + sigf(gf) * s_c[uu];
            s_c[uu] = cn;
            s_a[e][j][uu] = sigf(go) * tanhf(cn);
        }
    }
    gridbar(barbase, bark);
}

// ---- goal-LSTM layer phase (i,g,o gates; c=0) ----
__device__ void layer_phase(const float* __restrict__ W, size_t rstride,
                            const float* __restrict__ xin,
                            const float* __restrict__ bi, const float* __restrict__ bh,
                            float* __restrict__ outv,
                            int bid, int wib, int lane, int tid,
                            float* sh_x, float (*sh_part)[6]) {
    if (tid < 256) ((float4*)sh_x)[tid] = ((const float4*)xin)[tid];
    __syncthreads();
    const int slot = wib & 7, half = wib >> 3;
    const int u = bid * 8 + slot;
    const size_t co = (size_t)half * 512;
    float4 xv[4];
    {
        const float4* xs4 = (const float4*)(sh_x + co);
#pragma unroll
        for (int i = 0; i < 4; ++i) xv[i] = xs4[lane + (i << 5)];
    }
    float p0 = dot512r((const float4*)(W + (size_t)u * rstride + co), xv, lane);
    float p1 = dot512r((const float4*)(W + (size_t)(u + 2048) * rstride + co), xv, lane);
    float p2 = dot512r((const float4*)(W + (size_t)(u + 3072) * rstride + co), xv, lane);
    if (lane == 0) { sh_part[wib][0] = p0; sh_part[wib][1] = p1; sh_part[wib][2] = p2; }
    __syncthreads();
    if (wib == 0 && lane < 8) {
        int uu = bid * 8 + lane;
        float gi = sh_part[lane][0] + sh_part[lane + 8][0] + bi[uu] + bh[uu];
        float gg = sh_part[lane][1] + sh_part[lane + 8][1] + bi[uu + 2048] + bh[uu + 2048];
        float go = sh_part[lane][2] + sh_part[lane + 8][2] + bi[uu + 3072] + bh[uu + 3072];
        float cn = sigf(gi) * tanhf(gg);
        outv[uu] = sigf(go) * tanhf(cn);
    }
}

__global__ void __launch_bounds__(NT, 1)
va_kernel(const float* __restrict__ tsn,
          const float* __restrict__ W_fe,  const float* __restrict__ b_fe,
          const float* __restrict__ gW_ih0,const float* __restrict__ gW_ihR,
          const float* __restrict__ gb_ih, const float* __restrict__ gb_hh,
          const float* __restrict__ rW_ih, const float* __restrict__ rW_hh,
          const float* __restrict__ rb_ih, const float* __restrict__ rb_hh,
          const float* __restrict__ Wp,    const float* __restrict__ bp,
          const float* __restrict__ We2a,  const float* __restrict__ be2a,
          const float* __restrict__ We2v,  const float* __restrict__ be2v,
          const float* __restrict__ We2n,  const float* __restrict__ be2n,
          float* __restrict__ out) {
    const int tid  = threadIdx.x;
    const int lane = tid & 31;
    const int wib  = tid >> 5;

    __shared__ float sh_x[3072];
    __shared__ float sh_part[16][6];
    __shared__ float sh_pa[2][HD];
    __shared__ int sh_istar, sh_i0, sh_i1;
    __shared__ float sh_d9;
    __shared__ unsigned long long sh_base;

    if (tid == 0) {
        unsigned long long c0;
        asm volatile("ld.relaxed.gpu.global.u64 %0, [%1];" : "=l"(c0) : "l"(&s_cnt));
        sh_base = c0 & ~(unsigned long long)(NBC - 1);
    }
    __syncthreads();
    const unsigned long long base = sh_base;

    // =====================  STREAMER BLOCKS  =====================
    if (blockIdx.x >= NBC) {
        const int sid = (blockIdx.x - NBC) * NT + tid;
        const int nst = NSB * NT;

        // usage-order unthrottled prefetch (124 MB, fits L2)
        pf(W_fe, (size_t)HD * HD * 4, sid, nst);                             // 4 MB
        for (int idx = sid; idx < 3072 * 32; idx += nst) {                   // gW_ih0 used halves 12 MB
            int row = idx >> 5, ln = idx & 31;
            int rr = (row < 1024) ? row : row + 1024;                        // i rows, then g+o rows
            asm volatile("prefetch.global.L2 [%0];"
                         :: "l"(gW_ih0 + (size_t)rr * 2048 + ln * 32));
        }
#pragma unroll
        for (int l = 0; l < 4; ++l) {                                        // gW_ihR i,g,o: 12 MB each
            const float* bl = gW_ihR + (size_t)l * 4096 * 1024;
            pf(bl, (size_t)1024 * 1024 * 4, sid, nst);
            pf(bl + (size_t)2048 * 1024, (size_t)2048 * 1024 * 4, sid, nst);
        }
        pf(rW_ih, (size_t)4096 * 2048 * 4, sid, nst);                        // 32 MB
        pf(Wp, (size_t)1024 * 3072 * 4, sid, nst);                           // 12 MB
        pf(rW_hh, (size_t)4096 * 1024 * 4, sid, nst);                        // 16 MB

        // wait for fs (after compute barrier #2), then cur_action
        if (tid == 0) {
            unsigned long long v, t = base + 2ULL * NBC;
            do {
                asm volatile("ld.acquire.gpu.global.u64 %0, [%1];" : "=l"(v) : "l"(&s_cnt) : "memory");
                if (v < t) __nanosleep(128);
            } while (v < t);
        }
        __syncthreads();
        const int swid = (blockIdx.x - NBC) * WPB + wib;
        for (int r = swid; r < 2513; r += NSB * WPB) {
            float v = dot1024(We2a + (size_t)r * HD, s_fs, lane);
            if (lane == 0) out[OFF_CA + r] = v + be2a[r];
        }
        // re-warm prediction heads for P_pred (during E2)
        if (tid == 0) {
            unsigned long long v, t = base + 24ULL * NBC;
            do {
                asm volatile("ld.acquire.gpu.global.u64 %0, [%1];" : "=l"(v) : "l"(&s_cnt) : "memory");
                if (v < t) __nanosleep(256);
            } while (v < t);
        }
        __syncthreads();
        pf(We2a, (size_t)2513 * HD * 4, sid, nst);
        pf(We2v, 125 * 4096, sid, nst);
        pf(We2n, 352 * 4096, sid, nst);
        return;
    }

    // =====================  COMPUTE BLOCKS  =====================
    const int bid  = blockIdx.x;
    const int gwid = bid * WPB + wib;      // 0..2047
    const int gtid = bid * NT + tid;

    // ---------- P0: max-pool (ordered-uint REDG) + rb ----------
    {
        const int r0 = bid * 32;
        float m0 = -FLT_MAX, m1 = -FLT_MAX;
        for (int r = r0; r < r0 + 32; ++r) {
            m0 = fmaxf(m0, tsn[(size_t)r * HD + tid]);
            m1 = fmaxf(m1, tsn[(size_t)r * HD + 512 + tid]);
        }
        atomicMax(&s_maxu[tid], encf(m0));
        atomicMax(&s_maxu[tid + 512], encf(m1));
        for (int i = gtid; i < 4096; i += NBC * NT) s_rb[i] = rb_ih[i] + rb_hh[i];
    }
    gridbar(base, 1);

    // ---------- P2: fs = W_fe @ maxv + b_fe (split-dot) ----------
    {
        if (tid < 256) {
            uint4 k = ((const uint4*)s_maxu)[tid];
            float4 f;
            f.x = __uint_as_float((k.x & 0x80000000u) ? (k.x & 0x7FFFFFFFu) : ~k.x);
            f.y = __uint_as_float((k.y & 0x80000000u) ? (k.y & 0x7FFFFFFFu) : ~k.y);
            f.z = __uint_as_float((k.z & 0x80000000u) ? (k.z & 0x7FFFFFFFu) : ~k.z);
            f.w = __uint_as_float((k.w & 0x80000000u) ? (k.w & 0x7FFFFFFFu) : ~k.w);
            ((float4*)sh_x)[tid] = f;
        }
        __syncthreads();
        const int slot = wib & 7, half = wib >> 3;
        const int u = bid * 8 + slot;
        const size_t co = (size_t)half * 512;
        float4 xv[4];
        const float4* xs4 = (const float4*)(sh_x + co);
#pragma unroll
        for (int i = 0; i < 4; ++i) xv[i] = xs4[lane + (i << 5)];
        float p = dot512r((const float4*)(W_fe + (size_t)u * HD + co), xv, lane);
        if (lane == 0) sh_part[wib][0] = p;
        __syncthreads();
        if (wib == 0 && lane < 8) {
            int uu = bid * 8 + lane;
            s_fs[uu] = sh_part[lane][0] + sh_part[lane + 8][0] + b_fe[uu];
        }
    }
    gridbar(base, 2);

    // ---------- P3: goal layer 0 (stride 2048, x = fs only) ----------
    if (gtid < HD) s_maxu[gtid] = 0;   // reset for next call
    layer_phase(gW_ih0, 2048, s_fs, gb_ih, gb_hh, s_gh[0], bid, wib, lane, tid, sh_x, sh_part);
    gridbar(base, 3);

    // ---------- P4..P7: goal layers 1..4 ----------
    for (int l = 1; l <= 4; ++l) {
        layer_phase(gW_ihR + (size_t)(l - 1) * 4096 * 1024, 1024, s_gh[l - 1],
                    gb_ih + (size_t)l * 4096, gb_hh + (size_t)l * 4096, s_gh[l],
                    bid, wib, lane, tid, sh_x, sh_part);
        gridbar(base, 3 + l);
    }
    const float* goal = s_gh[4];

    // ---------- P8: E1 xpart(+h0,c0), Wp base, bd0 (balanced split) ----------
    {
        if (tid < 256) ((float4*)sh_x)[tid] = ((const float4*)s_fs)[tid];
        else           ((float4*)sh_x)[tid] = ((const float4*)goal)[tid - 256];
        __syncthreads();
        const int slot = wib & 7, half = wib >> 3;
        const int u = bid * 8 + slot;
        const size_t co = (size_t)half * 512;
        float4 xvF[4], xvG[4];
        {
            const float4* a4 = (const float4*)(sh_x + co);
            const float4* g4 = (const float4*)(sh_x + 1024 + co);
#pragma unroll
            for (int i = 0; i < 4; ++i) { xvF[i] = a4[lane + (i << 5)]; xvG[i] = g4[lane + (i << 5)]; }
        }
        const float* wr = rW_ih + (size_t)u * 2048 + 1024 + co;
        float p0 = dot512r((const float4*)wr, xvF, lane);
        float p1 = dot512r((const float4*)(wr + (size_t)1024 * 2048), xvF, lane);
        float p2 = dot512r((const float4*)(wr + (size_t)2048 * 2048), xvF, lane);
        float p3 = dot512r((const float4*)(wr + (size_t)3072 * 2048), xvF, lane);
        float p4 = dot512r((const float4*)(Wp + (size_t)u * 3072 + co), xvF, lane);
        float p5 = dot512r((const float4*)(Wp + (size_t)u * 3072 + 2048 + co), xvG, lane);
        if (lane == 0) {
            sh_part[wib][0] = p0; sh_part[wib][1] = p1; sh_part[wib][2] = p2;
            sh_part[wib][3] = p3; sh_part[wib][4] = p4; sh_part[wib][5] = p5;
        }
        if (bid == 127 && wib == 15) {   // bd0 from smem copies
            float acc = 0.0f;
            for (int i = lane; i < HD; i += 32) {
                float df = sh_x[i] - sh_x[1024 + i];
                acc = fmaf(df, df, acc);
            }
            acc = warp_red(acc);
            if (lane == 0) s_bd0 = acc * (1.0f / 1024.0f);
        }
        __syncthreads();
        if (wib == 0 && lane < 8) {
            int uu = bid * 8 + lane;
            float gi = sh_part[lane][0] + sh_part[lane + 8][0] + s_rb[uu];
            float gf = sh_part[lane][1] + sh_part[lane + 8][1] + s_rb[uu + 1024];
            float gg = sh_part[lane][2] + sh_part[lane + 8][2] + s_rb[uu + 2048];
            float go = sh_part[lane][3] + sh_part[lane + 8][3] + s_rb[uu + 3072];
            s_xpart[0][uu] = gi;          s_xpart[0][uu + 1024] = gf;
            s_xpart[0][uu + 2048] = gg;   s_xpart[0][uu + 3072] = go;
            float cn = sigf(gi) * tanhf(gg);
            s_c[uu] = cn;
            s_a[0][0][uu] = sigf(go) * tanhf(cn);
            s_base[0][uu] = sh_part[lane][4] + sh_part[lane + 8][4]
                          + sh_part[lane][5] + sh_part[lane + 8][5] + bp[uu];
        }
    }
    gridbar(base, 8);

    // ---------- Expansion 1 (j=1..10, barriers 9..18) ----------
    for (int j = 1; j <= 10; ++j)
        expand_phase(0, j, rW_hh, Wp, goal, bid, wib, lane, tid, sh_x, sh_part, base, 8 + j);

    // ---------- E2_preA: istar scan; xpart2/base2; f2in ----------
    {
        if (wib == 0) {
            float d9 = warp_sum1024(s_diff2[0][9], lane) * (1.0f / 1024.0f);
            if (lane == 0) {
                float bd = s_bd0, best = FLT_MAX; int istar = 0;
#pragma unroll
                for (int jj = 0; jj < 10; ++jj) {
                    float dj = (jj == 9) ? d9 : s_d[0][jj];
                    float s = bd - dj;
                    if (s < best) { best = s; istar = jj; }
                    if (dj < bd) bd = dj;
                }
                sh_istar = istar; sh_d9 = d9;
            }
        }
        __syncthreads();
        const int istar = sh_istar;
        if (bid == 0 && tid == 0) s_d[0][9] = sh_d9;
        const float* a2in = s_a[0][istar];
        const float* f2in = s_f[0][istar];
        for (int t = tid; t < 768; t += NT) {
            int which = t >> 8, idx = t & 255;
            const float* src = (which == 0) ? a2in : (which == 1) ? f2in : goal;
            ((float4*)sh_x)[t] = ((const float4*)src)[idx];
        }
        __syncthreads();
        for (int u = gwid; u < 5121; u += NWARPC) {
            if (u < 4096) {
                float v = dot1024_sm(rW_ih + (size_t)u * 2048, sh_x, lane)
                        + dot1024_sm(rW_ih + (size_t)u * 2048 + 1024, sh_x + 1024, lane);
                if (lane == 0) s_xpart[1][u] = v + s_rb[u];
            } else if (u < 5120) {
                int r = u - 4096;
                float v = dot1024_sm(Wp + (size_t)r * 3072, sh_x + 1024, lane)
                        + dot1024_sm(Wp + (size_t)r * 3072 + 2048, sh_x + 2048, lane);
                if (lane == 0) s_base[1][r] = v + bp[r];
            } else {
                for (int i = lane; i < HD; i += 32) out[OFF_F2 + i] = sh_x[1024 + i];
            }
        }
    }
    gridbar(base, 19);

    // ---------- E2_preB: h0/c0 for expansion 2 ----------
    if (gtid < HD) {
        float gi = s_xpart[1][gtid];
        float gg = s_xpart[1][gtid + 2048];
        float go = s_xpart[1][gtid + 3072];
        float cn = sigf(gi) * tanhf(gg);
        s_c[gtid] = cn;
        s_a[1][0][gtid] = sigf(go) * tanhf(cn);
    }
    gridbar(base, 20);

    // ---------- Expansion 2 (j=1..10, barriers 21..30) ----------
    for (int j = 1; j <= 10; ++j)
        expand_phase(1, j, rW_hh, Wp, goal, bid, wib, lane, tid, sh_x, sh_part, base, 20 + j);

    // ---------- Final: per-block scan + outputs ----------
    {
        if (wib == 0) {
            float d2_9 = warp_sum1024(s_diff2[1][9], lane) * (1.0f / 1024.0f);
            if (lane == 0) {
                float bd = s_bd0, best = FLT_MAX; int istar = 0;
                float s1[10], s2[10];
#pragma unroll
                for (int jj = 0; jj < 10; ++jj) {
                    float dj = s_d[0][jj];
                    s1[jj] = bd - dj;
                    if (s1[jj] < best) { best = s1[jj]; istar = jj; }
                    if (dj < bd) bd = dj;
                }
#pragma unroll
                for (int jj = 0; jj < 10; ++jj) {
                    float dj = (jj == 9) ? d2_9 : s_d[1][jj];
                    s2[jj] = bd - dj;
                    if (dj < bd) bd = dj;
                }
                float b0 = FLT_MAX, b1 = FLT_MAX; int i0 = 0, i1 = 0;
#pragma unroll
                for (int k = 0; k < 20; ++k) {
                    float v = (k < 10) ? ((k == istar) ? FLT_MAX : s1[k]) : s2[k - 10];
                    if (v < b0) { b1 = b0; i1 = i0; b0 = v; i0 = k; }
                    else if (v < b1) { b1 = v; i1 = k; }
                }
                sh_istar = istar; sh_i0 = i0; sh_i1 = i1;
            }
        }
        __syncthreads();
        const int istar = sh_istar;
        const float* a2in = s_a[0][istar];
        const float* f2in = s_f[0][istar];

        for (int t = tid; t < 2048; t += NT) {
            int which = t >> 10, col = t & 1023;
            int idx = which ? sh_i1 : sh_i0;
            float pa;
            if (idx < 10) pa = s_a[0][idx][col] * 0.5f;
            else          pa = (a2in[col] + s_a[1][idx - 10][col]) * (1.0f / 3.0f);
            sh_pa[which][col] = pa;
        }
        if (bid == 0) {
            for (int t = tid; t < 2048; t += NT) {
                int which = t >> 10, col = t & 1023;
                int idx = which ? sh_i1 : sh_i0;
                float pfv;
                if (idx < 10) pfv = (s_fs[col] + s_f[0][idx][col]) * 0.5f;
                else          pfv = (s_fs[col] + f2in[col] + s_f[1][idx - 10][col]) * (1.0f / 3.0f);
                out[OFF_PF + which * HD + col] = pfv;
                out[OFF_PG + which * HD + col] = goal[col];
            }
        }
        __syncthreads();

        // paired prediction dots: one row read serves both output rows
        for (int rr = gwid; rr < 2990; rr += NWARPC) {
            const float* W; const float* bias; int off, rows, r;
            if (rr < 2513)      { W = We2a; bias = be2a; off = OFF_PA; rows = 2513; r = rr; }
            else if (rr < 2638) { W = We2v; bias = be2v; off = OFF_PV; rows = 125;  r = rr - 2513; }
            else                { W = We2n; bias = be2n; off = OFF_PN; rows = 352;  r = rr - 2638; }
            const float4* row4 = (const float4*)(W + (size_t)r * HD);
            float a0 = 0.f, a1 = 0.f;
#pragma unroll
            for (int i = 0; i < 8; ++i) {
                int idx = lane + (i << 5);
                float4 w = row4[idx];
                float4 xa = ((const float4*)sh_pa[0])[idx];
                float4 xb = ((const float4*)sh_pa[1])[idx];
                a0 = fmaf(w.x, xa.x, fmaf(w.y, xa.y, fmaf(w.z, xa.z, fmaf(w.w, xa.w, a0))));
                a1 = fmaf(w.x, xb.x, fmaf(w.y, xb.y, fmaf(w.z, xb.z, fmaf(w.w, xb.w, a1))));
            }
            a0 = warp_red(a0); a1 = warp_red(a1);
            if (lane == 0) {
                out[off + r] = a0 + bias[r];
                out[off + rows + r] = a1 + bias[r];
            }
        }
    }
}

extern "C" void kernel_launch(void* const* d_in, const int* in_sizes, int n_in,
                              void* d_out, int out_size) {
    const float* tsn    = (const float*)d_in[0];
    const float* W_fe   = (const float*)d_in[1];
    const float* b_fe   = (const float*)d_in[2];
    const float* gW_ih0 = (const float*)d_in[3];
    const float* gW_ihR = (const float*)d_in[4];
    // d_in[5] = gW_hh : multiplied by zero hidden state everywhere -> unused
    const float* gb_ih  = (const float*)d_in[6];
    const float* gb_hh  = (const float*)d_in[7];
    const float* rW_ih  = (const float*)d_in[8];
    const float* rW_hh  = (const float*)d_in[9];
    const float* rb_ih  = (const float*)d_in[10];
    const float* rb_hh  = (const float*)d_in[11];
    const float* Wp     = (const float*)d_in[12];
    const float* bp     = (const float*)d_in[13];
    const float* We2a   = (const float*)d_in[14];
    const float* be2a   = (const float*)d_in[15];
    const float* We2v   = (const float*)d_in[16];
    const float* be2v   = (const float*)d_in[17];
    const float* We2n   = (const float*)d_in[18];
    const float* be2n   = (const float*)d_in[19];

    va_kernel<<<NB, NT>>>(tsn, W_fe, b_fe, gW_ih0, gW_ihR, gb_ih, gb_hh,
                          rW_ih, rW_hh, rb_ih, rb_hh, Wp, bp,
                          We2a, be2a, We2v, be2v, We2n, be2n,
                          (float*)d_out);
}